// round 2
// baseline (speedup 1.0000x reference)
#include <cuda_runtime.h>
#include <cuda_bf16.h>

// ---------------------------------------------------------------------------
// Problem constants
// ---------------------------------------------------------------------------
#define BATCH      4096
#define IN_DIM     16
#define LEVELS     17
#define ODIM       5
#define HDIM       1024
#define HS         3
#define KPAD       96            // IN_DIM + ODIM*16 = 96 (max K for input GEMM)
#define TOTW       (ODIM*LEVELS) // 85

// ---------------------------------------------------------------------------
// Scratch (device globals: no allocation allowed)
// ---------------------------------------------------------------------------
#define HN (BATCH * HDIM)
__device__ float g_h[4ll * HN];                 // [dirF:0/1 pingpong][dirB:2/3]
__device__ float g_prev[2ll * BATCH * KPAD];    // zero-padded prev, per dir
__device__ float g_tot[2ll * BATCH * TOTW];     // concatenated outs, per dir

// ---------------------------------------------------------------------------
// f32x2 packed-FMA helpers (FFMA2: only reachable via PTX fma.rn.f32x2)
// ---------------------------------------------------------------------------
__device__ __forceinline__ unsigned long long pk2(float lo, float hi) {
    unsigned long long r;
    asm("mov.b64 %0, {%1, %2};" : "=l"(r) : "f"(lo), "f"(hi));
    return r;
}
__device__ __forceinline__ unsigned long long fma2(unsigned long long a,
                                                   unsigned long long b,
                                                   unsigned long long c) {
    unsigned long long d;
    asm("fma.rn.f32x2 %0, %1, %2, %3;" : "=l"(d) : "l"(a), "l"(b), "l"(c));
    return d;
}
__device__ __forceinline__ void upk2(unsigned long long v, float& lo, float& hi) {
    asm("mov.b64 {%0, %1}, %2;" : "=f"(lo), "=f"(hi) : "l"(v));
}

// ---------------------------------------------------------------------------
// SGEMM: C = act(A @ B + bias), A[MxK] row-major, B[KxN] row-major.
// 128x128 block tile, BK=8, 256 threads, 8x8 microtile, f32x2 accumulators.
// gridDim.z selects direction (0: F-set pointers, 1: B-set pointers).
// ---------------------------------------------------------------------------
#define BM 128
#define BN 128
#define BK 8
#define TM 8
#define TN 8

__global__ void __launch_bounds__(256, 2)
sgemm_bias_act(const float* __restrict__ A0, const float* __restrict__ A1,
               const float* __restrict__ B0, const float* __restrict__ B1,
               const float* __restrict__ bias0, const float* __restrict__ bias1,
               float* __restrict__ C0, float* __restrict__ C1,
               int M, int N, int K, int doRelu)
{
    const float* A    = blockIdx.z ? A1 : A0;
    const float* B    = blockIdx.z ? B1 : B0;
    const float* bias = blockIdx.z ? bias1 : bias0;
    float*       C    = blockIdx.z ? C1 : C0;

    __shared__ float As[BK][BM];
    __shared__ float Bs[BK][BN];

    const int tid = threadIdx.x;
    const int threadRow = tid >> 4;    // 0..15
    const int threadCol = tid & 15;    // 0..15

    const int cRow = blockIdx.y * BM;
    const int cCol = blockIdx.x * BN;

    A += (long long)cRow * K;
    B += cCol;
    C += (long long)cRow * N + cCol;

    const int innerRowA = tid >> 1;          // 0..127
    const int innerColA = (tid & 1) * 4;     // 0 or 4
    const int innerRowB = tid >> 5;          // 0..7
    const int innerColB = (tid & 31) * 4;    // 0..124

    unsigned long long acc[TM][TN / 2];
#pragma unroll
    for (int m = 0; m < TM; ++m)
#pragma unroll
        for (int n = 0; n < TN / 2; ++n) acc[m][n] = 0ull;

    const int numTiles = K / BK;

    float4 aReg = *reinterpret_cast<const float4*>(A + innerRowA * K + innerColA);
    float4 bReg = *reinterpret_cast<const float4*>(B + innerRowB * N + innerColB);

    for (int t = 0; t < numTiles; ++t) {
        // stage current tile into smem (A transposed)
        As[innerColA + 0][innerRowA] = aReg.x;
        As[innerColA + 1][innerRowA] = aReg.y;
        As[innerColA + 2][innerRowA] = aReg.z;
        As[innerColA + 3][innerRowA] = aReg.w;
        *reinterpret_cast<float4*>(&Bs[innerRowB][innerColB]) = bReg;
        __syncthreads();

        // prefetch next tile into registers (overlaps with compute below)
        if (t + 1 < numTiles) {
            aReg = *reinterpret_cast<const float4*>(A + (t + 1) * BK + innerRowA * K + innerColA);
            bReg = *reinterpret_cast<const float4*>(B + (long long)(t + 1) * BK * N + innerRowB * N + innerColB);
        }

#pragma unroll
        for (int k = 0; k < BK; ++k) {
            float4 a0 = *reinterpret_cast<const float4*>(&As[k][threadRow * TM]);
            float4 a1 = *reinterpret_cast<const float4*>(&As[k][threadRow * TM + 4]);
            float4 b0 = *reinterpret_cast<const float4*>(&Bs[k][threadCol * TN]);
            float4 b1 = *reinterpret_cast<const float4*>(&Bs[k][threadCol * TN + 4]);

            unsigned long long bp[4];
            bp[0] = pk2(b0.x, b0.y);
            bp[1] = pk2(b0.z, b0.w);
            bp[2] = pk2(b1.x, b1.y);
            bp[3] = pk2(b1.z, b1.w);

            float av[8] = {a0.x, a0.y, a0.z, a0.w, a1.x, a1.y, a1.z, a1.w};
#pragma unroll
            for (int m = 0; m < TM; ++m) {
                unsigned long long ap = pk2(av[m], av[m]);
#pragma unroll
                for (int n = 0; n < TN / 2; ++n)
                    acc[m][n] = fma2(ap, bp[n], acc[m][n]);
            }
        }
        __syncthreads();
    }

    // epilogue: bias + optional relu, vectorized stores
    const float* bp = bias + cCol + threadCol * TN;
    float bv[TN];
#pragma unroll
    for (int n = 0; n < TN; ++n) bv[n] = bp[n];

#pragma unroll
    for (int m = 0; m < TM; ++m) {
        float v[TN];
#pragma unroll
        for (int n = 0; n < TN / 2; ++n) upk2(acc[m][n], v[2 * n], v[2 * n + 1]);
#pragma unroll
        for (int n = 0; n < TN; ++n) {
            v[n] += bv[n];
            if (doRelu) v[n] = fmaxf(v[n], 0.0f);
        }
        float* crow = C + (long long)(threadRow * TM + m) * N + threadCol * TN;
        *reinterpret_cast<float4*>(crow)     = make_float4(v[0], v[1], v[2], v[3]);
        *reinterpret_cast<float4*>(crow + 4) = make_float4(v[4], v[5], v[6], v[7]);
    }
}

// ---------------------------------------------------------------------------
// init: prev[:, :16] = x, prev[:, 16:96] = 0 (both directions)
// ---------------------------------------------------------------------------
__global__ void init_prev(const float* __restrict__ x,
                          float* __restrict__ prevF, float* __restrict__ prevB)
{
    int idx = blockIdx.x * blockDim.x + threadIdx.x;
    if (idx < BATCH * KPAD) {
        int b = idx / KPAD, c = idx % KPAD;
        float v = (c < IN_DIM) ? x[b * IN_DIM + c] : 0.0f;
        prevF[idx] = v;
        prevB[idx] = v;
    }
}

// ---------------------------------------------------------------------------
// out-proj: out5 = h @ Wout[i] + bout[i]; write into tot and prev
// grid (BATCH, 1, 2), 256 threads
// ---------------------------------------------------------------------------
__global__ void out_proj(const float* __restrict__ h0, const float* __restrict__ h1,
                         const float* __restrict__ Wf, const float* __restrict__ Wb,
                         const float* __restrict__ bf, const float* __restrict__ bb,
                         float* __restrict__ totF, float* __restrict__ totB,
                         float* __restrict__ prevF, float* __restrict__ prevB,
                         int level)
{
    const int b   = blockIdx.x;
    const int dir = blockIdx.z;
    const float* h    = (dir ? h1 : h0) + (long long)b * HDIM;
    const float* Wout = dir ? Wb : Wf;
    const float* bout = dir ? bb : bf;
    float* tot  = dir ? totB : totF;
    float* prev = dir ? prevB : prevF;

    __shared__ float sh[HDIM];
    const int tid = threadIdx.x;
    reinterpret_cast<float4*>(sh)[tid] = reinterpret_cast<const float4*>(h)[tid];
    __syncthreads();

    const int warp = tid >> 5, lane = tid & 31;
    if (warp < ODIM) {
        float acc = 0.0f;
        for (int k = lane; k < HDIM; k += 32)
            acc += sh[k] * Wout[k * ODIM + warp];
#pragma unroll
        for (int off = 16; off > 0; off >>= 1)
            acc += __shfl_down_sync(0xffffffffu, acc, off);
        if (lane == 0) {
            float val = acc + bout[warp];
            tot[b * TOTW + level * ODIM + warp] = val;
            if (level < LEVELS - 1)
                prev[b * KPAD + IN_DIM + level * ODIM + warp] = val;
        }
    }
}

// ---------------------------------------------------------------------------
// attention + final linear, one block per batch row, 128 threads
// ---------------------------------------------------------------------------
__global__ void attn_final(const float* __restrict__ totF, const float* __restrict__ totB,
                           const float* __restrict__ W1, const float* __restrict__ W2,
                           const float* __restrict__ W3, const float* __restrict__ W4,
                           const float* __restrict__ b4, float* __restrict__ out)
{
    const int b = blockIdx.x;
    __shared__ float tf[ODIM][LEVELS], tb[ODIM][LEVELS];
    __shared__ float q[LEVELS][ODIM], kk[ODIM][LEVELS], v[LEVELS][ODIM];
    __shared__ float attn[LEVELS][LEVELS];
    __shared__ float res[TOTW];
    __shared__ float w1[25], w2[25], w3[25];

    const int tid = threadIdx.x;
    if (tid < TOTW) {
        // tf[d][t] = totF[b, d*17+t]; tb[d][t] = totB[b, d*17 + (16-t)]
        reinterpret_cast<float*>(tf)[tid] = totF[b * TOTW + tid];
        int d = tid / LEVELS, t = tid % LEVELS;
        tb[d][t] = totB[b * TOTW + d * LEVELS + (LEVELS - 1 - t)];
    }
    if (tid < 25) { w1[tid] = W1[tid]; w2[tid] = W2[tid]; w3[tid] = W3[tid]; }
    __syncthreads();

    if (tid < TOTW) {
        int t = tid / ODIM, e = tid % ODIM;
        float sq = 0.f, sk = 0.f, sv = 0.f;
#pragma unroll
        for (int d = 0; d < ODIM; ++d) {
            sq += tf[d][t] * w1[d * ODIM + e];
            sk += tb[d][t] * w2[d * ODIM + e];
            sv += tb[d][t] * w3[d * ODIM + e];
        }
        q[t][e] = sq; kk[e][t] = sk; v[t][e] = sv;
    }
    __syncthreads();

    for (int idx = tid; idx < LEVELS * LEVELS; idx += blockDim.x) {
        int t = idx / LEVELS, s = idx % LEVELS;
        float sc = 0.f;
#pragma unroll
        for (int e = 0; e < ODIM; ++e) sc += q[t][e] * kk[e][s];
        attn[t][s] = sc;
    }
    __syncthreads();

    // softmax over t (axis=1 of (b,t,s)) for each s
    if (tid < LEVELS) {
        int s = tid;
        float mx = -1e30f;
        for (int t = 0; t < LEVELS; ++t) mx = fmaxf(mx, attn[t][s]);
        float sm = 0.f;
        for (int t = 0; t < LEVELS; ++t) { float e = expf(attn[t][s] - mx); attn[t][s] = e; sm += e; }
        float inv = 1.0f / sm;
        for (int t = 0; t < LEVELS; ++t) attn[t][s] *= inv;
    }
    __syncthreads();

    if (tid < TOTW) {
        int t = tid / ODIM, e = tid % ODIM;
        float r = 0.f;
        for (int s = 0; s < LEVELS; ++s) r += attn[t][s] * v[s][e];
        res[tid] = r;   // flat index t*5+e matches reshape(B, 17, 5)->(B,85)
    }
    __syncthreads();

    if (tid < TOTW) {
        int o = tid;
        float y = b4[o];
        for (int j = 0; j < TOTW; ++j) y += res[j] * W4[j * TOTW + o];
        out[(long long)b * TOTW + o] = y;
    }
}

// ---------------------------------------------------------------------------
// Host launcher (graph-capturable: kernel launches only)
// ---------------------------------------------------------------------------
extern "C" void kernel_launch(void* const* d_in, const int* in_sizes, int n_in,
                              void* d_out, int out_size)
{
    const float* x      = (const float*)d_in[0];
    const float* Win_f  = (const float*)d_in[1];
    const float* bin_f  = (const float*)d_in[2];
    const float* Win_b  = (const float*)d_in[3];
    const float* bin_b  = (const float*)d_in[4];
    const float* Wblk   = (const float*)d_in[5];
    const float* bblk   = (const float*)d_in[6];
    const float* Wout_f = (const float*)d_in[7];
    const float* bout_f = (const float*)d_in[8];
    const float* Wout_b = (const float*)d_in[9];
    const float* bout_b = (const float*)d_in[10];
    const float* W1     = (const float*)d_in[11];
    const float* W2     = (const float*)d_in[12];
    const float* W3     = (const float*)d_in[13];
    const float* W4     = (const float*)d_in[14];
    const float* b4     = (const float*)d_in[15];
    float* out = (float*)d_out;

    float *hbuf, *prevbuf, *totbuf;
    cudaGetSymbolAddress((void**)&hbuf, g_h);
    cudaGetSymbolAddress((void**)&prevbuf, g_prev);
    cudaGetSymbolAddress((void**)&totbuf, g_tot);

    float* hF[2]  = { hbuf,          hbuf + HN };
    float* hB[2]  = { hbuf + 2ll*HN, hbuf + 3ll*HN };
    float* prevF  = prevbuf;
    float* prevB  = prevbuf + (long long)BATCH * KPAD;
    float* totF   = totbuf;
    float* totB   = totbuf + (long long)BATCH * TOTW;

    init_prev<<<(BATCH * KPAD + 255) / 256, 256>>>(x, prevF, prevB);

    dim3 gg(HDIM / BN, BATCH / BM, 2);   // (8, 32, 2)
    for (int i = 0; i < LEVELS; ++i) {
        // input GEMM: h0 = prev_pad @ Win[i] + bin[i]  (K=96, padding rows of
        // Win multiply zero prev cols -> no contribution)
        sgemm_bias_act<<<gg, 256>>>(prevF, prevB,
                                    Win_f + (long long)i * KPAD * HDIM,
                                    Win_b + (long long)i * KPAD * HDIM,
                                    bin_f + i * HDIM, bin_b + i * HDIM,
                                    hF[0], hB[0],
                                    BATCH, HDIM, KPAD, 0);
        int cur = 0;
        for (int j = 0; j < HS; ++j) {
            sgemm_bias_act<<<gg, 256>>>(hF[cur], hB[cur],
                                        Wblk + (long long)j * HDIM * HDIM,
                                        Wblk + (long long)j * HDIM * HDIM,
                                        bblk + j * HDIM, bblk + j * HDIM,
                                        hF[cur ^ 1], hB[cur ^ 1],
                                        BATCH, HDIM, HDIM, 1);
            cur ^= 1;
        }
        // after 3 block layers, result is in buffer index 1
        out_proj<<<dim3(BATCH, 1, 2), 256>>>(hF[1], hB[1],
                                             Wout_f + (long long)i * HDIM * ODIM,
                                             Wout_b + (long long)i * HDIM * ODIM,
                                             bout_f + i * ODIM, bout_b + i * ODIM,
                                             totF, totB, prevF, prevB, i);
    }

    attn_final<<<BATCH, 128>>>(totF, totB, W1, W2, W3, W4, b4, out);
}

// round 3
// speedup vs baseline: 1.0008x; 1.0008x over previous
#include <cuda_runtime.h>
#include <cuda_bf16.h>

// ---------------------------------------------------------------------------
// Problem constants
// ---------------------------------------------------------------------------
#define BATCH      4096
#define IN_DIM     16
#define LEVELS     17
#define ODIM       5
#define HDIM       1024
#define HS         3
#define KPAD       96            // IN_DIM + ODIM*16 = 96 (max K for input GEMM)
#define TOTW       (ODIM*LEVELS) // 85

// ---------------------------------------------------------------------------
// Scratch (device globals: no allocation allowed)
// ---------------------------------------------------------------------------
#define HN (BATCH * HDIM)
__device__ float g_h[4ll * HN];                 // [dirF:0/1 pingpong][dirB:2/3]
__device__ float g_prev[2ll * BATCH * KPAD];    // zero-padded prev, per dir
__device__ float g_tot[2ll * BATCH * TOTW];     // concatenated outs, per dir

// ---------------------------------------------------------------------------
// f32x2 packed-FMA helpers (FFMA2: only reachable via PTX fma.rn.f32x2)
// ---------------------------------------------------------------------------
__device__ __forceinline__ unsigned long long pk2(float lo, float hi) {
    unsigned long long r;
    asm("mov.b64 %0, {%1, %2};" : "=l"(r) : "f"(lo), "f"(hi));
    return r;
}
__device__ __forceinline__ unsigned long long fma2(unsigned long long a,
                                                   unsigned long long b,
                                                   unsigned long long c) {
    unsigned long long d;
    asm("fma.rn.f32x2 %0, %1, %2, %3;" : "=l"(d) : "l"(a), "l"(b), "l"(c));
    return d;
}
__device__ __forceinline__ void upk2(unsigned long long v, float& lo, float& hi) {
    asm("mov.b64 {%0, %1}, %2;" : "=f"(lo), "=f"(hi) : "l"(v));
}

// ---------------------------------------------------------------------------
// SGEMM: C = act(A @ B + bias), A[MxK] row-major, B[KxN] row-major.
// 128x128 block tile, BK=8, 256 threads, 8x8 microtile, f32x2 accumulators.
// gridDim.z selects direction (0: F-set pointers, 1: B-set pointers).
// ---------------------------------------------------------------------------
#define BM 128
#define BN 128
#define BK 8
#define TM 8
#define TN 8

__global__ void __launch_bounds__(256, 2)
sgemm_bias_act(const float* __restrict__ A0, const float* __restrict__ A1,
               const float* __restrict__ B0, const float* __restrict__ B1,
               const float* __restrict__ bias0, const float* __restrict__ bias1,
               float* __restrict__ C0, float* __restrict__ C1,
               int M, int N, int K, int doRelu)
{
    const float* A    = blockIdx.z ? A1 : A0;
    const float* B    = blockIdx.z ? B1 : B0;
    const float* bias = blockIdx.z ? bias1 : bias0;
    float*       C    = blockIdx.z ? C1 : C0;

    __shared__ float As[BK][BM];
    __shared__ float Bs[BK][BN];

    const int tid = threadIdx.x;
    const int threadRow = tid >> 4;    // 0..15
    const int threadCol = tid & 15;    // 0..15

    const int cRow = blockIdx.y * BM;
    const int cCol = blockIdx.x * BN;

    A += (long long)cRow * K;
    B += cCol;
    C += (long long)cRow * N + cCol;

    const int innerRowA = tid >> 1;          // 0..127
    const int innerColA = (tid & 1) * 4;     // 0 or 4
    const int innerRowB = tid >> 5;          // 0..7
    const int innerColB = (tid & 31) * 4;    // 0..124

    unsigned long long acc[TM][TN / 2];
#pragma unroll
    for (int m = 0; m < TM; ++m)
#pragma unroll
        for (int n = 0; n < TN / 2; ++n) acc[m][n] = 0ull;

    const int numTiles = K / BK;

    float4 aReg = *reinterpret_cast<const float4*>(A + innerRowA * K + innerColA);
    float4 bReg = *reinterpret_cast<const float4*>(B + innerRowB * N + innerColB);

    for (int t = 0; t < numTiles; ++t) {
        // stage current tile into smem (A transposed)
        As[innerColA + 0][innerRowA] = aReg.x;
        As[innerColA + 1][innerRowA] = aReg.y;
        As[innerColA + 2][innerRowA] = aReg.z;
        As[innerColA + 3][innerRowA] = aReg.w;
        *reinterpret_cast<float4*>(&Bs[innerRowB][innerColB]) = bReg;
        __syncthreads();

        // prefetch next tile into registers (overlaps with compute below)
        if (t + 1 < numTiles) {
            aReg = *reinterpret_cast<const float4*>(A + (t + 1) * BK + innerRowA * K + innerColA);
            bReg = *reinterpret_cast<const float4*>(B + (long long)(t + 1) * BK * N + innerRowB * N + innerColB);
        }

#pragma unroll
        for (int k = 0; k < BK; ++k) {
            float4 a0 = *reinterpret_cast<const float4*>(&As[k][threadRow * TM]);
            float4 a1 = *reinterpret_cast<const float4*>(&As[k][threadRow * TM + 4]);
            float4 b0 = *reinterpret_cast<const float4*>(&Bs[k][threadCol * TN]);
            float4 b1 = *reinterpret_cast<const float4*>(&Bs[k][threadCol * TN + 4]);

            unsigned long long bp[4];
            bp[0] = pk2(b0.x, b0.y);
            bp[1] = pk2(b0.z, b0.w);
            bp[2] = pk2(b1.x, b1.y);
            bp[3] = pk2(b1.z, b1.w);

            float av[8] = {a0.x, a0.y, a0.z, a0.w, a1.x, a1.y, a1.z, a1.w};
#pragma unroll
            for (int m = 0; m < TM; ++m) {
                unsigned long long ap = pk2(av[m], av[m]);
#pragma unroll
                for (int n = 0; n < TN / 2; ++n)
                    acc[m][n] = fma2(ap, bp[n], acc[m][n]);
            }
        }
        __syncthreads();
    }

    // epilogue: bias + optional relu, vectorized stores
    const float* bp = bias + cCol + threadCol * TN;
    float bv[TN];
#pragma unroll
    for (int n = 0; n < TN; ++n) bv[n] = bp[n];

#pragma unroll
    for (int m = 0; m < TM; ++m) {
        float v[TN];
#pragma unroll
        for (int n = 0; n < TN / 2; ++n) upk2(acc[m][n], v[2 * n], v[2 * n + 1]);
#pragma unroll
        for (int n = 0; n < TN; ++n) {
            v[n] += bv[n];
            if (doRelu) v[n] = fmaxf(v[n], 0.0f);
        }
        float* crow = C + (long long)(threadRow * TM + m) * N + threadCol * TN;
        *reinterpret_cast<float4*>(crow)     = make_float4(v[0], v[1], v[2], v[3]);
        *reinterpret_cast<float4*>(crow + 4) = make_float4(v[4], v[5], v[6], v[7]);
    }
}

// ---------------------------------------------------------------------------
// init: prev[:, :16] = x, prev[:, 16:96] = 0 (both directions)
// ---------------------------------------------------------------------------
__global__ void init_prev(const float* __restrict__ x,
                          float* __restrict__ prevF, float* __restrict__ prevB)
{
    int idx = blockIdx.x * blockDim.x + threadIdx.x;
    if (idx < BATCH * KPAD) {
        int b = idx / KPAD, c = idx % KPAD;
        float v = (c < IN_DIM) ? x[b * IN_DIM + c] : 0.0f;
        prevF[idx] = v;
        prevB[idx] = v;
    }
}

// ---------------------------------------------------------------------------
// out-proj: out5 = h @ Wout[i] + bout[i]; write into tot and prev
// grid (BATCH, 1, 2), 256 threads
// ---------------------------------------------------------------------------
__global__ void out_proj(const float* __restrict__ h0, const float* __restrict__ h1,
                         const float* __restrict__ Wf, const float* __restrict__ Wb,
                         const float* __restrict__ bf, const float* __restrict__ bb,
                         float* __restrict__ totF, float* __restrict__ totB,
                         float* __restrict__ prevF, float* __restrict__ prevB,
                         int level)
{
    const int b   = blockIdx.x;
    const int dir = blockIdx.z;
    const float* h    = (dir ? h1 : h0) + (long long)b * HDIM;
    const float* Wout = dir ? Wb : Wf;
    const float* bout = dir ? bb : bf;
    float* tot  = dir ? totB : totF;
    float* prev = dir ? prevB : prevF;

    __shared__ float sh[HDIM];
    const int tid = threadIdx.x;
    reinterpret_cast<float4*>(sh)[tid] = reinterpret_cast<const float4*>(h)[tid];
    __syncthreads();

    const int warp = tid >> 5, lane = tid & 31;
    if (warp < ODIM) {
        float acc = 0.0f;
        for (int k = lane; k < HDIM; k += 32)
            acc += sh[k] * Wout[k * ODIM + warp];
#pragma unroll
        for (int off = 16; off > 0; off >>= 1)
            acc += __shfl_down_sync(0xffffffffu, acc, off);
        if (lane == 0) {
            float val = acc + bout[warp];
            tot[b * TOTW + level * ODIM + warp] = val;
            if (level < LEVELS - 1)
                prev[b * KPAD + IN_DIM + level * ODIM + warp] = val;
        }
    }
}

// ---------------------------------------------------------------------------
// attention + final linear, one block per batch row, 128 threads
// ---------------------------------------------------------------------------
__global__ void attn_final(const float* __restrict__ totF, const float* __restrict__ totB,
                           const float* __restrict__ W1, const float* __restrict__ W2,
                           const float* __restrict__ W3, const float* __restrict__ W4,
                           const float* __restrict__ b4, float* __restrict__ out)
{
    const int b = blockIdx.x;
    __shared__ float tf[ODIM][LEVELS], tb[ODIM][LEVELS];
    __shared__ float q[LEVELS][ODIM], kk[ODIM][LEVELS], v[LEVELS][ODIM];
    __shared__ float attn[LEVELS][LEVELS];
    __shared__ float res[TOTW];
    __shared__ float w1[25], w2[25], w3[25];

    const int tid = threadIdx.x;
    if (tid < TOTW) {
        // tf[d][t] = totF[b, d*17+t]; tb[d][t] = totB[b, d*17 + (16-t)]
        reinterpret_cast<float*>(tf)[tid] = totF[b * TOTW + tid];
        int d = tid / LEVELS, t = tid % LEVELS;
        tb[d][t] = totB[b * TOTW + d * LEVELS + (LEVELS - 1 - t)];
    }
    if (tid < 25) { w1[tid] = W1[tid]; w2[tid] = W2[tid]; w3[tid] = W3[tid]; }
    __syncthreads();

    if (tid < TOTW) {
        int t = tid / ODIM, e = tid % ODIM;
        float sq = 0.f, sk = 0.f, sv = 0.f;
#pragma unroll
        for (int d = 0; d < ODIM; ++d) {
            sq += tf[d][t] * w1[d * ODIM + e];
            sk += tb[d][t] * w2[d * ODIM + e];
            sv += tb[d][t] * w3[d * ODIM + e];
        }
        q[t][e] = sq; kk[e][t] = sk; v[t][e] = sv;
    }
    __syncthreads();

    for (int idx = tid; idx < LEVELS * LEVELS; idx += blockDim.x) {
        int t = idx / LEVELS, s = idx % LEVELS;
        float sc = 0.f;
#pragma unroll
        for (int e = 0; e < ODIM; ++e) sc += q[t][e] * kk[e][s];
        attn[t][s] = sc;
    }
    __syncthreads();

    // softmax over t (axis=1 of (b,t,s)) for each s
    if (tid < LEVELS) {
        int s = tid;
        float mx = -1e30f;
        for (int t = 0; t < LEVELS; ++t) mx = fmaxf(mx, attn[t][s]);
        float sm = 0.f;
        for (int t = 0; t < LEVELS; ++t) { float e = expf(attn[t][s] - mx); attn[t][s] = e; sm += e; }
        float inv = 1.0f / sm;
        for (int t = 0; t < LEVELS; ++t) attn[t][s] *= inv;
    }
    __syncthreads();

    if (tid < TOTW) {
        int t = tid / ODIM, e = tid % ODIM;
        float r = 0.f;
        for (int s = 0; s < LEVELS; ++s) r += attn[t][s] * v[s][e];
        res[tid] = r;   // flat index t*5+e matches reshape(B, 17, 5)->(B,85)
    }
    __syncthreads();

    if (tid < TOTW) {
        int o = tid;
        float y = b4[o];
        for (int j = 0; j < TOTW; ++j) y += res[j] * W4[j * TOTW + o];
        out[(long long)b * TOTW + o] = y;
    }
}

// ---------------------------------------------------------------------------
// Host launcher (graph-capturable: kernel launches only)
// ---------------------------------------------------------------------------
extern "C" void kernel_launch(void* const* d_in, const int* in_sizes, int n_in,
                              void* d_out, int out_size)
{
    const float* x      = (const float*)d_in[0];
    const float* Win_f  = (const float*)d_in[1];
    const float* bin_f  = (const float*)d_in[2];
    const float* Win_b  = (const float*)d_in[3];
    const float* bin_b  = (const float*)d_in[4];
    const float* Wblk   = (const float*)d_in[5];
    const float* bblk   = (const float*)d_in[6];
    const float* Wout_f = (const float*)d_in[7];
    const float* bout_f = (const float*)d_in[8];
    const float* Wout_b = (const float*)d_in[9];
    const float* bout_b = (const float*)d_in[10];
    const float* W1     = (const float*)d_in[11];
    const float* W2     = (const float*)d_in[12];
    const float* W3     = (const float*)d_in[13];
    const float* W4     = (const float*)d_in[14];
    const float* b4     = (const float*)d_in[15];
    float* out = (float*)d_out;

    float *hbuf, *prevbuf, *totbuf;
    cudaGetSymbolAddress((void**)&hbuf, g_h);
    cudaGetSymbolAddress((void**)&prevbuf, g_prev);
    cudaGetSymbolAddress((void**)&totbuf, g_tot);

    float* hF[2]  = { hbuf,          hbuf + HN };
    float* hB[2]  = { hbuf + 2ll*HN, hbuf + 3ll*HN };
    float* prevF  = prevbuf;
    float* prevB  = prevbuf + (long long)BATCH * KPAD;
    float* totF   = totbuf;
    float* totB   = totbuf + (long long)BATCH * TOTW;

    init_prev<<<(BATCH * KPAD + 255) / 256, 256>>>(x, prevF, prevB);

    dim3 gg(HDIM / BN, BATCH / BM, 2);   // (8, 32, 2)
    for (int i = 0; i < LEVELS; ++i) {
        // input GEMM: h0 = prev_pad @ Win[i] + bin[i]  (K=96, padding rows of
        // Win multiply zero prev cols -> no contribution)
        sgemm_bias_act<<<gg, 256>>>(prevF, prevB,
                                    Win_f + (long long)i * KPAD * HDIM,
                                    Win_b + (long long)i * KPAD * HDIM,
                                    bin_f + i * HDIM, bin_b + i * HDIM,
                                    hF[0], hB[0],
                                    BATCH, HDIM, KPAD, 0);
        int cur = 0;
        for (int j = 0; j < HS; ++j) {
            sgemm_bias_act<<<gg, 256>>>(hF[cur], hB[cur],
                                        Wblk + (long long)j * HDIM * HDIM,
                                        Wblk + (long long)j * HDIM * HDIM,
                                        bblk + j * HDIM, bblk + j * HDIM,
                                        hF[cur ^ 1], hB[cur ^ 1],
                                        BATCH, HDIM, HDIM, 1);
            cur ^= 1;
        }
        // after 3 block layers, result is in buffer index 1
        out_proj<<<dim3(BATCH, 1, 2), 256>>>(hF[1], hB[1],
                                             Wout_f + (long long)i * HDIM * ODIM,
                                             Wout_b + (long long)i * HDIM * ODIM,
                                             bout_f + i * ODIM, bout_b + i * ODIM,
                                             totF, totB, prevF, prevB, i);
    }

    attn_final<<<BATCH, 128>>>(totF, totB, W1, W2, W3, W4, b4, out);
}

// round 6
// speedup vs baseline: 2.4123x; 2.4103x over previous
#include <cuda_runtime.h>
#include <cuda_bf16.h>
#include <cstdint>

#define BATCH 4096
#define IN_DIM 16
#define LEVELS 17
#define ODIM 5
#define HDIM 1024
#define HS 3
#define KP 128
#define TOTW (ODIM*LEVELS)
#define HN (BATCH*HDIM)

// ---------------- scratch ----------------
__device__ __nv_bfloat16 g_hhi[4ull*HN], g_hlo[4ull*HN];
__device__ __nv_bfloat16 g_phi[2ull*BATCH*KP], g_plo[2ull*BATCH*KP];
__device__ __nv_bfloat16 g_wihi[34ull*HDIM*KP], g_wilo[34ull*HDIM*KP];
__device__ __nv_bfloat16 g_wbhi[3ull*HDIM*HDIM], g_wblo[3ull*HDIM*HDIM];
__device__ float g_tot[2ull*BATCH*TOTW];

// ---------------- helpers ----------------
__device__ __forceinline__ uint32_t smem_u32(const void* p){ return (uint32_t)__cvta_generic_to_shared(p); }
__device__ __forceinline__ void cpa16(uint32_t d, const void* s){
    asm volatile("cp.async.cg.shared.global [%0], [%1], 16;" :: "r"(d),"l"(s)); }
#define CP_COMMIT() asm volatile("cp.async.commit_group;" ::: "memory")

__device__ __forceinline__ void ldsm4(uint32_t* r, uint32_t a){
    asm volatile("ldmatrix.sync.aligned.m8n8.x4.shared.b16 {%0,%1,%2,%3}, [%4];"
        : "=r"(r[0]),"=r"(r[1]),"=r"(r[2]),"=r"(r[3]) : "r"(a));
}
__device__ __forceinline__ void mma16816(float* d, const uint32_t* a, const uint32_t* b){
    asm volatile("mma.sync.aligned.m16n8k16.row.col.f32.bf16.bf16.f32 "
        "{%0,%1,%2,%3}, {%4,%5,%6,%7}, {%8,%9}, {%0,%1,%2,%3};"
        : "+f"(d[0]),"+f"(d[1]),"+f"(d[2]),"+f"(d[3])
        : "r"(a[0]),"r"(a[1]),"r"(a[2]),"r"(a[3]), "r"(b[0]),"r"(b[1]));
}

// ---------------- GEMM: C[4096xHDIM] = act(A @ B^T + bias), bf16x3 via mma.sync ----------------
// A[4096,AKD] hi/lo row-major; B[HDIM,AKD] hi/lo (pre-transposed, same K stride).
// 128x128 CTA tile, BK=32, 3-stage cp.async ring. blockIdx.z = direction.
#define STG_SZ 32768   // Ahi 8K | Alo 8K | Bhi 8K | Blo 8K
#define SMEM_DYN (3*STG_SZ)

__global__ void __launch_bounds__(256)
gemm_bf16x3(const __nv_bfloat16* __restrict__ Ah0, const __nv_bfloat16* __restrict__ Al0,
            const __nv_bfloat16* __restrict__ Ah1, const __nv_bfloat16* __restrict__ Al1, int AKD,
            const __nv_bfloat16* __restrict__ Bh0, const __nv_bfloat16* __restrict__ Bl0,
            const __nv_bfloat16* __restrict__ Bh1, const __nv_bfloat16* __restrict__ Bl1,
            const float* __restrict__ bias0, const float* __restrict__ bias1,
            __nv_bfloat16* __restrict__ oH0, __nv_bfloat16* __restrict__ oL0,
            __nv_bfloat16* __restrict__ oH1, __nv_bfloat16* __restrict__ oL1,
            int K, int relu)
{
    extern __shared__ char smem[];
    __shared__ float sbias[128];
    const int tid=threadIdx.x, wid=tid>>5, lane=tid&31, dir=blockIdx.z;
    const int Nbase=blockIdx.x*128, Mbase=blockIdx.y*128;
    const int warpM=wid&1, warpN=wid>>1;

    const __nv_bfloat16* Ah = dir?Ah1:Ah0; const __nv_bfloat16* Al = dir?Al1:Al0;
    const __nv_bfloat16* Bh = dir?Bh1:Bh0; const __nv_bfloat16* Bl = dir?Bl1:Bl0;
    const float* bias = dir?bias1:bias0;
    __nv_bfloat16* oH = dir?oH1:oH0; __nv_bfloat16* oL = dir?oL1:oL0;

    if(tid<128) sbias[tid]=bias[Nbase+tid];
    const uint32_t sbase=smem_u32(smem);

    // per-stage loader: 512 16B-chunks per sub-buffer, 2 per thread
    auto load_stage=[&](int s){
        const uint32_t sb = sbase + (uint32_t)(s%3)*STG_SZ;
        const int kb = s*32;
        #pragma unroll
        for(int i=0;i<2;++i){
            int idx = tid + i*256;          // 0..511
            int r = idx>>2, c = idx&3;
            uint32_t dst = sb + (uint32_t)(r*64 + ((c ^ ((r>>1)&3))*16));
            size_t ga = (size_t)(Mbase+r)*AKD + kb + c*8;
            size_t gb = (size_t)(Nbase+r)*AKD + kb + c*8;
            cpa16(dst,         Ah+ga);
            cpa16(dst+8192,    Al+ga);
            cpa16(dst+16384,   Bh+gb);
            cpa16(dst+24576,   Bl+gb);
        }
        CP_COMMIT();
    };

    float acc[4][4][4];
    #pragma unroll
    for(int m=0;m<4;++m)
        #pragma unroll
        for(int n=0;n<4;++n)
            #pragma unroll
            for(int i=0;i<4;++i) acc[m][n][i]=0.f;

    const int NS = K>>5;          // K/32, always >= 4 here
    load_stage(0); load_stage(1);

    for(int s=0;s<NS;++s){
        if(s+1<NS) asm volatile("cp.async.wait_group 1;":::"memory");
        else       asm volatile("cp.async.wait_group 0;":::"memory");
        __syncthreads();
        if(s+2<NS) load_stage(s+2);

        const uint32_t sb = sbase + (uint32_t)(s%3)*STG_SZ;
        #pragma unroll
        for(int ks=0;ks<2;++ks){
            uint32_t a[2][4][4];
            #pragma unroll
            for(int mt=0;mt<4;++mt){
                int r = warpM*64 + mt*16 + (lane&15);
                int cc = (ks*2 + (lane>>4)) ^ ((r>>1)&3);
                uint32_t ad = sb + (uint32_t)(r*64 + cc*16);
                ldsm4(a[0][mt], ad);
                ldsm4(a[1][mt], ad + 8192);
            }
            uint32_t b[2][4][2];
            #pragma unroll
            for(int ntp=0;ntp<2;++ntp){
                int grp = lane>>3;
                int tile = ntp*2 + (grp>>1);
                int n = warpN*32 + tile*8 + (lane&7);
                int cc = (ks*2 + (grp&1)) ^ ((n>>1)&3);
                uint32_t ad = sb + 16384u + (uint32_t)(n*64 + cc*16);
                uint32_t t[4];
                ldsm4(t, ad);
                b[0][2*ntp][0]=t[0]; b[0][2*ntp][1]=t[1];
                b[0][2*ntp+1][0]=t[2]; b[0][2*ntp+1][1]=t[3];
                ldsm4(t, ad + 8192);
                b[1][2*ntp][0]=t[0]; b[1][2*ntp][1]=t[1];
                b[1][2*ntp+1][0]=t[2]; b[1][2*ntp+1][1]=t[3];
            }
            #pragma unroll
            for(int mt=0;mt<4;++mt)
                #pragma unroll
                for(int nt=0;nt<4;++nt){
                    mma16816(acc[mt][nt], a[0][mt], b[0][nt]);  // hi*hi
                    mma16816(acc[mt][nt], a[0][mt], b[1][nt]);  // hi*lo
                    mma16816(acc[mt][nt], a[1][mt], b[0][nt]);  // lo*hi
                }
        }
    }

    // epilogue: bias + relu, hi/lo split, direct stores
    #pragma unroll
    for(int mt=0;mt<4;++mt){
        #pragma unroll
        for(int nt=0;nt<4;++nt){
            int rl = warpM*64 + mt*16 + (lane>>2);
            int cl = warpN*32 + nt*8 + (lane&3)*2;
            #pragma unroll
            for(int h=0;h<2;++h){
                int row = Mbase + rl + h*8;
                float v0 = acc[mt][nt][2*h]   + sbias[cl];
                float v1 = acc[mt][nt][2*h+1] + sbias[cl+1];
                if(relu){ v0=fmaxf(v0,0.f); v1=fmaxf(v1,0.f); }
                __nv_bfloat16 h0=__float2bfloat16(v0), h1=__float2bfloat16(v1);
                __nv_bfloat162 hv; hv.x=h0; hv.y=h1;
                __nv_bfloat162 lv; lv.x=__float2bfloat16(v0-__bfloat162float(h0));
                                   lv.y=__float2bfloat16(v1-__bfloat162float(h1));
                size_t o = (size_t)row*HDIM + Nbase + cl;
                *reinterpret_cast<uint32_t*>(oH+o) = *reinterpret_cast<uint32_t*>(&hv);
                *reinterpret_cast<uint32_t*>(oL+o) = *reinterpret_cast<uint32_t*>(&lv);
            }
        }
    }
}

// ---------------- transpose + hi/lo split: dst[n][k]=split(src[k][n]), k>=KD -> 0 ----------------
__global__ void transpose_split(const float* __restrict__ src, int KD, int ND, int KOUT,
                                __nv_bfloat16* __restrict__ dH, __nv_bfloat16* __restrict__ dL)
{
    __shared__ float t[32][33];
    const int mz=blockIdx.z;
    src+=(size_t)mz*KD*ND; dH+=(size_t)mz*ND*KOUT; dL+=(size_t)mz*ND*KOUT;
    const int kt=blockIdx.x*32, nt=blockIdx.y*32, tx=threadIdx.x, ty=threadIdx.y;
    for(int r=ty;r<32;r+=8){ int k=kt+r; t[r][tx]=(k<KD)?src[(size_t)k*ND+nt+tx]:0.f; }
    __syncthreads();
    for(int r=ty;r<32;r+=8){ int n=nt+r, k=kt+tx;
        float v=t[tx][r]; __nv_bfloat16 h=__float2bfloat16(v);
        dH[(size_t)n*KOUT+k]=h; dL[(size_t)n*KOUT+k]=__float2bfloat16(v-__bfloat162float(h)); }
}

// ---------------- init prev ----------------
__global__ void init_prev_k(const float* __restrict__ x,
                            __nv_bfloat16* __restrict__ phi, __nv_bfloat16* __restrict__ plo)
{
    int i=blockIdx.x*256+threadIdx.x; if(i>=BATCH*KP) return;
    int b=i>>7, c=i&127;
    float v=(c<IN_DIM)?x[b*IN_DIM+c]:0.f;
    __nv_bfloat16 h=__float2bfloat16(v);
    __nv_bfloat16 l=__float2bfloat16(v-__bfloat162float(h));
    size_t o2=(size_t)BATCH*KP;
    phi[i]=h; plo[i]=l; phi[i+o2]=h; plo[i+o2]=l;
}

// ---------------- out-proj ----------------
__global__ void out_proj(const __nv_bfloat16* __restrict__ hHi, const __nv_bfloat16* __restrict__ hLo,
                         int hi0, int hi1,
                         const float* __restrict__ Wf, const float* __restrict__ Wb,
                         const float* __restrict__ bf, const float* __restrict__ bb,
                         float* __restrict__ totbuf,
                         __nv_bfloat16* __restrict__ phi, __nv_bfloat16* __restrict__ plo,
                         int level)
{
    const int b=blockIdx.x, dir=blockIdx.z, tid=threadIdx.x;
    const size_t hoff=(size_t)(dir?hi1:hi0)*HN + (size_t)b*HDIM;
    const float* Wout = dir?Wb:Wf; const float* bout = dir?bb:bf;
    float* tot = totbuf + (size_t)dir*BATCH*TOTW;
    __nv_bfloat16* ph = phi + (size_t)dir*BATCH*KP;
    __nv_bfloat16* pl = plo + (size_t)dir*BATCH*KP;

    __shared__ float sh[HDIM];
    #pragma unroll
    for(int q=0;q<4;++q){ int k=tid+q*256;
        sh[k]=__bfloat162float(hHi[hoff+k])+__bfloat162float(hLo[hoff+k]); }
    __syncthreads();
    const int warp=tid>>5, lane=tid&31;
    if(warp<ODIM){
        float acc=0.f;
        for(int k=lane;k<HDIM;k+=32) acc+=sh[k]*Wout[k*ODIM+warp];
        #pragma unroll
        for(int off=16;off>0;off>>=1) acc+=__shfl_down_sync(0xffffffffu,acc,off);
        if(lane==0){
            float val=acc+bout[warp];
            tot[b*TOTW+level*ODIM+warp]=val;
            if(level<LEVELS-1){
                int pc=b*KP+IN_DIM+level*ODIM+warp;
                __nv_bfloat16 h=__float2bfloat16(val);
                ph[pc]=h; pl[pc]=__float2bfloat16(val-__bfloat162float(h));
            }
        }
    }
}

// ---------------- attention + final linear ----------------
__global__ void attn_final(const float* __restrict__ totbuf,
                           const float* __restrict__ W1, const float* __restrict__ W2,
                           const float* __restrict__ W3, const float* __restrict__ W4,
                           const float* __restrict__ b4, float* __restrict__ out)
{
    const int b=blockIdx.x;
    const float* totF=totbuf; const float* totB=totbuf+(size_t)BATCH*TOTW;
    __shared__ float tf[ODIM][LEVELS], tb[ODIM][LEVELS];
    __shared__ float q[LEVELS][ODIM], kk[ODIM][LEVELS], v[LEVELS][ODIM];
    __shared__ float attn[LEVELS][LEVELS], res[TOTW], w1[25], w2[25], w3[25];
    const int tid=threadIdx.x;
    if(tid<TOTW){
        reinterpret_cast<float*>(tf)[tid]=totF[b*TOTW+tid];
        int d=tid/LEVELS, t=tid%LEVELS;
        tb[d][t]=totB[b*TOTW+d*LEVELS+(LEVELS-1-t)];
    }
    if(tid<25){ w1[tid]=W1[tid]; w2[tid]=W2[tid]; w3[tid]=W3[tid]; }
    __syncthreads();
    if(tid<TOTW){
        int t=tid/ODIM, e=tid%ODIM;
        float sq=0.f,sk=0.f,sv=0.f;
        #pragma unroll
        for(int d=0;d<ODIM;++d){
            sq+=tf[d][t]*w1[d*ODIM+e]; sk+=tb[d][t]*w2[d*ODIM+e]; sv+=tb[d][t]*w3[d*ODIM+e]; }
        q[t][e]=sq; kk[e][t]=sk; v[t][e]=sv;
    }
    __syncthreads();
    for(int idx=tid;idx<LEVELS*LEVELS;idx+=blockDim.x){
        int t=idx/LEVELS, s=idx%LEVELS;
        float sc=0.f;
        #pragma unroll
        for(int e=0;e<ODIM;++e) sc+=q[t][e]*kk[e][s];
        attn[t][s]=sc;
    }
    __syncthreads();
    if(tid<LEVELS){
        int s=tid; float mx=-1e30f;
        for(int t=0;t<LEVELS;++t) mx=fmaxf(mx,attn[t][s]);
        float sm=0.f;
        for(int t=0;t<LEVELS;++t){ float e=expf(attn[t][s]-mx); attn[t][s]=e; sm+=e; }
        float inv=1.f/sm;
        for(int t=0;t<LEVELS;++t) attn[t][s]*=inv;
    }
    __syncthreads();
    if(tid<TOTW){
        int t=tid/ODIM, e=tid%ODIM; float r=0.f;
        for(int s=0;s<LEVELS;++s) r+=attn[t][s]*v[s][e];
        res[tid]=r;
    }
    __syncthreads();
    if(tid<TOTW){
        int o=tid; float y=b4[o];
        for(int j=0;j<TOTW;++j) y+=res[j]*W4[j*TOTW+o];
        out[(size_t)b*TOTW+o]=y;
    }
}

// ---------------- host ----------------
extern "C" void kernel_launch(void* const* d_in, const int* in_sizes, int n_in,
                              void* d_out, int out_size)
{
    const float* x=(const float*)d_in[0];
    const float* Win_f=(const float*)d_in[1];  const float* bin_f=(const float*)d_in[2];
    const float* Win_b=(const float*)d_in[3];  const float* bin_b=(const float*)d_in[4];
    const float* Wblk=(const float*)d_in[5];   const float* bblk=(const float*)d_in[6];
    const float* Wout_f=(const float*)d_in[7]; const float* bout_f=(const float*)d_in[8];
    const float* Wout_b=(const float*)d_in[9]; const float* bout_b=(const float*)d_in[10];
    const float* W1=(const float*)d_in[11]; const float* W2=(const float*)d_in[12];
    const float* W3=(const float*)d_in[13]; const float* W4=(const float*)d_in[14];
    const float* b4=(const float*)d_in[15];
    float* out=(float*)d_out;

    __nv_bfloat16 *hhi,*hlo,*phi,*plo,*wihi,*wilo,*wbhi,*wblo; float* tot;
    cudaGetSymbolAddress((void**)&hhi,g_hhi);   cudaGetSymbolAddress((void**)&hlo,g_hlo);
    cudaGetSymbolAddress((void**)&phi,g_phi);   cudaGetSymbolAddress((void**)&plo,g_plo);
    cudaGetSymbolAddress((void**)&wihi,g_wihi); cudaGetSymbolAddress((void**)&wilo,g_wilo);
    cudaGetSymbolAddress((void**)&wbhi,g_wbhi); cudaGetSymbolAddress((void**)&wblo,g_wblo);
    cudaGetSymbolAddress((void**)&tot,g_tot);

    cudaFuncSetAttribute(gemm_bf16x3, cudaFuncAttributeMaxDynamicSharedMemorySize, SMEM_DYN);

    const size_t WI=(size_t)HDIM*KP;
    transpose_split<<<dim3(KP/32,HDIM/32,LEVELS),dim3(32,8)>>>(Win_f,96,HDIM,KP,wihi,wilo);
    transpose_split<<<dim3(KP/32,HDIM/32,LEVELS),dim3(32,8)>>>(Win_b,96,HDIM,KP,wihi+17*WI,wilo+17*WI);
    transpose_split<<<dim3(HDIM/32,HDIM/32,HS),dim3(32,8)>>>(Wblk,HDIM,HDIM,HDIM,wbhi,wblo);
    init_prev_k<<<(BATCH*KP+255)/256,256>>>(x,phi,plo);

    dim3 gg(HDIM/128, BATCH/128, 2);  // (8, 32, 2)
    const size_t PK=(size_t)BATCH*KP, WB=(size_t)HDIM*HDIM;
    for(int i=0;i<LEVELS;++i){
        gemm_bf16x3<<<gg,256,SMEM_DYN>>>(phi,plo,phi+PK,plo+PK,KP,
            wihi+(size_t)i*WI, wilo+(size_t)i*WI, wihi+(size_t)(17+i)*WI, wilo+(size_t)(17+i)*WI,
            bin_f+i*HDIM, bin_b+i*HDIM,
            hhi, hlo, hhi+2ull*HN, hlo+2ull*HN, KP, 0);
        int cur=0;
        for(int j=0;j<HS;++j){
            gemm_bf16x3<<<gg,256,SMEM_DYN>>>(
                hhi+(size_t)cur*HN, hlo+(size_t)cur*HN, hhi+(size_t)(2+cur)*HN, hlo+(size_t)(2+cur)*HN, HDIM,
                wbhi+(size_t)j*WB, wblo+(size_t)j*WB, wbhi+(size_t)j*WB, wblo+(size_t)j*WB,
                bblk+j*HDIM, bblk+j*HDIM,
                hhi+(size_t)(cur^1)*HN, hlo+(size_t)(cur^1)*HN,
                hhi+(size_t)(2+(cur^1))*HN, hlo+(size_t)(2+(cur^1))*HN, HDIM, 1);
            cur^=1;
        }
        out_proj<<<dim3(BATCH,1,2),256>>>(hhi,hlo,1,3,
            Wout_f+(size_t)i*HDIM*ODIM, Wout_b+(size_t)i*HDIM*ODIM,
            bout_f+i*ODIM, bout_b+i*ODIM, tot, phi, plo, i);
    }
    attn_final<<<BATCH,128>>>(tot,W1,W2,W3,W4,b4,out);
}

// round 7
// speedup vs baseline: 2.7403x; 1.1360x over previous
#include <cuda_runtime.h>
#include <cuda_bf16.h>
#include <cstdint>

#define BATCH 4096
#define IN_DIM 16
#define LEVELS 17
#define ODIM 5
#define HDIM 1024
#define HS 3
#define KP 128
#define TOTW (ODIM*LEVELS)
#define HN (BATCH*HDIM)

// ---------------- scratch ----------------
__device__ __nv_bfloat16 g_hhi[4ull*HN], g_hlo[4ull*HN];
__device__ __nv_bfloat16 g_phi[2ull*BATCH*KP], g_plo[2ull*BATCH*KP];
__device__ __nv_bfloat16 g_wihi[34ull*HDIM*KP], g_wilo[34ull*HDIM*KP];
__device__ __nv_bfloat16 g_wbhi[3ull*HDIM*HDIM], g_wblo[3ull*HDIM*HDIM];
__device__ float g_tot[2ull*BATCH*TOTW];

// ---------------- helpers ----------------
__device__ __forceinline__ uint32_t smem_u32(const void* p){ return (uint32_t)__cvta_generic_to_shared(p); }
__device__ __forceinline__ void cpa16(uint32_t d, const void* s){
    asm volatile("cp.async.cg.shared.global [%0], [%1], 16;" :: "r"(d),"l"(s)); }
#define CP_COMMIT() asm volatile("cp.async.commit_group;" ::: "memory")

__device__ __forceinline__ void ldsm4(uint32_t* r, uint32_t a){
    asm volatile("ldmatrix.sync.aligned.m8n8.x4.shared.b16 {%0,%1,%2,%3}, [%4];"
        : "=r"(r[0]),"=r"(r[1]),"=r"(r[2]),"=r"(r[3]) : "r"(a));
}
__device__ __forceinline__ void mma16816(float* d, const uint32_t* a, const uint32_t* b){
    asm volatile("mma.sync.aligned.m16n8k16.row.col.f32.bf16.bf16.f32 "
        "{%0,%1,%2,%3}, {%4,%5,%6,%7}, {%8,%9}, {%0,%1,%2,%3};"
        : "+f"(d[0]),"+f"(d[1]),"+f"(d[2]),"+f"(d[3])
        : "r"(a[0]),"r"(a[1]),"r"(a[2]),"r"(a[3]), "r"(b[0]),"r"(b[1]));
}

// ---------------- GEMM: C[4096xHDIM] = act(A @ B^T + bias), bf16x3 via mma.sync ----------------
// A[4096,AKD] hi/lo row-major; B[HDIM,AKD] hi/lo (pre-transposed, same K stride).
// 128x128 CTA tile, BK=32, 3-stage cp.async ring, 2 CTAs/SM. blockIdx.z = direction.
#define STG_SZ 32768   // Ahi 8K | Alo 8K | Bhi 8K | Blo 8K
#define SMEM_DYN (3*STG_SZ)

__global__ void __launch_bounds__(256, 2)
gemm_bf16x3(const __nv_bfloat16* __restrict__ Ah0, const __nv_bfloat16* __restrict__ Al0,
            const __nv_bfloat16* __restrict__ Ah1, const __nv_bfloat16* __restrict__ Al1, int AKD,
            const __nv_bfloat16* __restrict__ Bh0, const __nv_bfloat16* __restrict__ Bl0,
            const __nv_bfloat16* __restrict__ Bh1, const __nv_bfloat16* __restrict__ Bl1,
            const float* __restrict__ bias0, const float* __restrict__ bias1,
            __nv_bfloat16* __restrict__ oH0, __nv_bfloat16* __restrict__ oL0,
            __nv_bfloat16* __restrict__ oH1, __nv_bfloat16* __restrict__ oL1,
            int K, int relu)
{
    extern __shared__ char smem[];
    __shared__ float sbias[128];
    const int tid=threadIdx.x, wid=tid>>5, lane=tid&31, dir=blockIdx.z;
    const int Nbase=blockIdx.x*128, Mbase=blockIdx.y*128;
    const int warpM=wid&1, warpN=wid>>1;

    const __nv_bfloat16* Ah = dir?Ah1:Ah0; const __nv_bfloat16* Al = dir?Al1:Al0;
    const __nv_bfloat16* Bh = dir?Bh1:Bh0; const __nv_bfloat16* Bl = dir?Bl1:Bl0;
    const float* bias = dir?bias1:bias0;
    __nv_bfloat16* oH = dir?oH1:oH0; __nv_bfloat16* oL = dir?oL1:oL0;

    if(tid<128) sbias[tid]=bias[Nbase+tid];
    const uint32_t sbase=smem_u32(smem);

    // per-stage loader: 512 16B-chunks per sub-buffer, 2 per thread
    auto load_stage=[&](int s){
        const uint32_t sb = sbase + (uint32_t)(s%3)*STG_SZ;
        const int kb = s*32;
        #pragma unroll
        for(int i=0;i<2;++i){
            int idx = tid + i*256;          // 0..511
            int r = idx>>2, c = idx&3;
            uint32_t dst = sb + (uint32_t)(r*64 + ((c ^ ((r>>1)&3))*16));
            size_t ga = (size_t)(Mbase+r)*AKD + kb + c*8;
            size_t gb = (size_t)(Nbase+r)*AKD + kb + c*8;
            cpa16(dst,         Ah+ga);
            cpa16(dst+8192,    Al+ga);
            cpa16(dst+16384,   Bh+gb);
            cpa16(dst+24576,   Bl+gb);
        }
        CP_COMMIT();
    };

    float acc[4][4][4];
    #pragma unroll
    for(int m=0;m<4;++m)
        #pragma unroll
        for(int n=0;n<4;++n)
            #pragma unroll
            for(int i=0;i<4;++i) acc[m][n][i]=0.f;

    const int NS = K>>5;          // K/32, always >= 4 here
    load_stage(0); load_stage(1);

    for(int s=0;s<NS;++s){
        if(s+1<NS) asm volatile("cp.async.wait_group 1;":::"memory");
        else       asm volatile("cp.async.wait_group 0;":::"memory");
        __syncthreads();
        if(s+2<NS) load_stage(s+2);

        const uint32_t sb = sbase + (uint32_t)(s%3)*STG_SZ;
        #pragma unroll
        for(int ks=0;ks<2;++ks){
            // B fragments for this k16 slice (hi+lo): 16 regs live
            uint32_t b[2][4][2];
            #pragma unroll
            for(int ntp=0;ntp<2;++ntp){
                int grp = lane>>3;
                int tile = ntp*2 + (grp>>1);
                int n = warpN*32 + tile*8 + (lane&7);
                int cc = (ks*2 + (grp&1)) ^ ((n>>1)&3);
                uint32_t ad = sb + 16384u + (uint32_t)(n*64 + cc*16);
                uint32_t t[4];
                ldsm4(t, ad);
                b[0][2*ntp][0]=t[0]; b[0][2*ntp][1]=t[1];
                b[0][2*ntp+1][0]=t[2]; b[0][2*ntp+1][1]=t[3];
                ldsm4(t, ad + 8192);
                b[1][2*ntp][0]=t[0]; b[1][2*ntp][1]=t[1];
                b[1][2*ntp+1][0]=t[2]; b[1][2*ntp+1][1]=t[3];
            }
            // A fragments loaded per-mt to bound register liveness (8 regs)
            #pragma unroll
            for(int mt=0;mt<4;++mt){
                int r = warpM*64 + mt*16 + (lane&15);
                int cc = (ks*2 + (lane>>4)) ^ ((r>>1)&3);
                uint32_t ad = sb + (uint32_t)(r*64 + cc*16);
                uint32_t a0[4], a1[4];
                ldsm4(a0, ad);
                ldsm4(a1, ad + 8192);
                #pragma unroll
                for(int nt=0;nt<4;++nt){
                    mma16816(acc[mt][nt], a0, b[0][nt]);  // hi*hi
                    mma16816(acc[mt][nt], a0, b[1][nt]);  // hi*lo
                    mma16816(acc[mt][nt], a1, b[0][nt]);  // lo*hi
                }
            }
        }
    }

    // epilogue: bias + relu, hi/lo split, direct stores
    #pragma unroll
    for(int mt=0;mt<4;++mt){
        #pragma unroll
        for(int nt=0;nt<4;++nt){
            int rl = warpM*64 + mt*16 + (lane>>2);
            int cl = warpN*32 + nt*8 + (lane&3)*2;
            #pragma unroll
            for(int h=0;h<2;++h){
                int row = Mbase + rl + h*8;
                float v0 = acc[mt][nt][2*h]   + sbias[cl];
                float v1 = acc[mt][nt][2*h+1] + sbias[cl+1];
                if(relu){ v0=fmaxf(v0,0.f); v1=fmaxf(v1,0.f); }
                __nv_bfloat16 h0=__float2bfloat16(v0), h1=__float2bfloat16(v1);
                __nv_bfloat162 hv; hv.x=h0; hv.y=h1;
                __nv_bfloat162 lv; lv.x=__float2bfloat16(v0-__bfloat162float(h0));
                                   lv.y=__float2bfloat16(v1-__bfloat162float(h1));
                size_t o = (size_t)row*HDIM + Nbase + cl;
                *reinterpret_cast<uint32_t*>(oH+o) = *reinterpret_cast<uint32_t*>(&hv);
                *reinterpret_cast<uint32_t*>(oL+o) = *reinterpret_cast<uint32_t*>(&lv);
            }
        }
    }
}

// ---------------- transpose + hi/lo split: dst[n][k]=split(src[k][n]), k>=KD -> 0 ----------------
__global__ void transpose_split(const float* __restrict__ src, int KD, int ND, int KOUT,
                                __nv_bfloat16* __restrict__ dH, __nv_bfloat16* __restrict__ dL)
{
    __shared__ float t[32][33];
    const int mz=blockIdx.z;
    src+=(size_t)mz*KD*ND; dH+=(size_t)mz*ND*KOUT; dL+=(size_t)mz*ND*KOUT;
    const int kt=blockIdx.x*32, nt=blockIdx.y*32, tx=threadIdx.x, ty=threadIdx.y;
    for(int r=ty;r<32;r+=8){ int k=kt+r; t[r][tx]=(k<KD)?src[(size_t)k*ND+nt+tx]:0.f; }
    __syncthreads();
    for(int r=ty;r<32;r+=8){ int n=nt+r, k=kt+tx;
        float v=t[tx][r]; __nv_bfloat16 h=__float2bfloat16(v);
        dH[(size_t)n*KOUT+k]=h; dL[(size_t)n*KOUT+k]=__float2bfloat16(v-__bfloat162float(h)); }
}

// ---------------- init prev ----------------
__global__ void init_prev_k(const float* __restrict__ x,
                            __nv_bfloat16* __restrict__ phi, __nv_bfloat16* __restrict__ plo)
{
    int i=blockIdx.x*256+threadIdx.x; if(i>=BATCH*KP) return;
    int b=i>>7, c=i&127;
    float v=(c<IN_DIM)?x[b*IN_DIM+c]:0.f;
    __nv_bfloat16 h=__float2bfloat16(v);
    __nv_bfloat16 l=__float2bfloat16(v-__bfloat162float(h));
    size_t o2=(size_t)BATCH*KP;
    phi[i]=h; plo[i]=l; phi[i+o2]=h; plo[i+o2]=l;
}

// ---------------- out-proj ----------------
__global__ void out_proj(const __nv_bfloat16* __restrict__ hHi, const __nv_bfloat16* __restrict__ hLo,
                         int hi0, int hi1,
                         const float* __restrict__ Wf, const float* __restrict__ Wb,
                         const float* __restrict__ bf, const float* __restrict__ bb,
                         float* __restrict__ totbuf,
                         __nv_bfloat16* __restrict__ phi, __nv_bfloat16* __restrict__ plo,
                         int level)
{
    const int b=blockIdx.x, dir=blockIdx.z, tid=threadIdx.x;
    const size_t hoff=(size_t)(dir?hi1:hi0)*HN + (size_t)b*HDIM;
    const float* Wout = dir?Wb:Wf; const float* bout = dir?bb:bf;
    float* tot = totbuf + (size_t)dir*BATCH*TOTW;
    __nv_bfloat16* ph = phi + (size_t)dir*BATCH*KP;
    __nv_bfloat16* pl = plo + (size_t)dir*BATCH*KP;

    __shared__ float sh[HDIM];
    #pragma unroll
    for(int q=0;q<4;++q){ int k=tid+q*256;
        sh[k]=__bfloat162float(hHi[hoff+k])+__bfloat162float(hLo[hoff+k]); }
    __syncthreads();
    const int warp=tid>>5, lane=tid&31;
    if(warp<ODIM){
        float acc=0.f;
        for(int k=lane;k<HDIM;k+=32) acc+=sh[k]*Wout[k*ODIM+warp];
        #pragma unroll
        for(int off=16;off>0;off>>=1) acc+=__shfl_down_sync(0xffffffffu,acc,off);
        if(lane==0){
            float val=acc+bout[warp];
            tot[b*TOTW+level*ODIM+warp]=val;
            if(level<LEVELS-1){
                int pc=b*KP+IN_DIM+level*ODIM+warp;
                __nv_bfloat16 h=__float2bfloat16(val);
                ph[pc]=h; pl[pc]=__float2bfloat16(val-__bfloat162float(h));
            }
        }
    }
}

// ---------------- attention + final linear ----------------
__global__ void attn_final(const float* __restrict__ totbuf,
                           const float* __restrict__ W1, const float* __restrict__ W2,
                           const float* __restrict__ W3, const float* __restrict__ W4,
                           const float* __restrict__ b4, float* __restrict__ out)
{
    const int b=blockIdx.x;
    const float* totF=totbuf; const float* totB=totbuf+(size_t)BATCH*TOTW;
    __shared__ float tf[ODIM][LEVELS], tb[ODIM][LEVELS];
    __shared__ float q[LEVELS][ODIM], kk[ODIM][LEVELS], v[LEVELS][ODIM];
    __shared__ float attn[LEVELS][LEVELS], res[TOTW], w1[25], w2[25], w3[25];
    const int tid=threadIdx.x;
    if(tid<TOTW){
        reinterpret_cast<float*>(tf)[tid]=totF[b*TOTW+tid];
        int d=tid/LEVELS, t=tid%LEVELS;
        tb[d][t]=totB[b*TOTW+d*LEVELS+(LEVELS-1-t)];
    }
    if(tid<25){ w1[tid]=W1[tid]; w2[tid]=W2[tid]; w3[tid]=W3[tid]; }
    __syncthreads();
    if(tid<TOTW){
        int t=tid/ODIM, e=tid%ODIM;
        float sq=0.f,sk=0.f,sv=0.f;
        #pragma unroll
        for(int d=0;d<ODIM;++d){
            sq+=tf[d][t]*w1[d*ODIM+e]; sk+=tb[d][t]*w2[d*ODIM+e]; sv+=tb[d][t]*w3[d*ODIM+e]; }
        q[t][e]=sq; kk[e][t]=sk; v[t][e]=sv;
    }
    __syncthreads();
    for(int idx=tid;idx<LEVELS*LEVELS;idx+=blockDim.x){
        int t=idx/LEVELS, s=idx%LEVELS;
        float sc=0.f;
        #pragma unroll
        for(int e=0;e<ODIM;++e) sc+=q[t][e]*kk[e][s];
        attn[t][s]=sc;
    }
    __syncthreads();
    if(tid<LEVELS){
        int s=tid; float mx=-1e30f;
        for(int t=0;t<LEVELS;++t) mx=fmaxf(mx,attn[t][s]);
        float sm=0.f;
        for(int t=0;t<LEVELS;++t){ float e=expf(attn[t][s]-mx); attn[t][s]=e; sm+=e; }
        float inv=1.f/sm;
        for(int t=0;t<LEVELS;++t) attn[t][s]*=inv;
    }
    __syncthreads();
    if(tid<TOTW){
        int t=tid/ODIM, e=tid%ODIM; float r=0.f;
        for(int s=0;s<LEVELS;++s) r+=attn[t][s]*v[s][e];
        res[tid]=r;
    }
    __syncthreads();
    if(tid<TOTW){
        int o=tid; float y=b4[o];
        for(int j=0;j<TOTW;++j) y+=res[j]*W4[j*TOTW+o];
        out[(size_t)b*TOTW+o]=y;
    }
}

// ---------------- host ----------------
extern "C" void kernel_launch(void* const* d_in, const int* in_sizes, int n_in,
                              void* d_out, int out_size)
{
    const float* x=(const float*)d_in[0];
    const float* Win_f=(const float*)d_in[1];  const float* bin_f=(const float*)d_in[2];
    const float* Win_b=(const float*)d_in[3];  const float* bin_b=(const float*)d_in[4];
    const float* Wblk=(const float*)d_in[5];   const float* bblk=(const float*)d_in[6];
    const float* Wout_f=(const float*)d_in[7]; const float* bout_f=(const float*)d_in[8];
    const float* Wout_b=(const float*)d_in[9]; const float* bout_b=(const float*)d_in[10];
    const float* W1=(const float*)d_in[11]; const float* W2=(const float*)d_in[12];
    const float* W3=(const float*)d_in[13]; const float* W4=(const float*)d_in[14];
    const float* b4=(const float*)d_in[15];
    float* out=(float*)d_out;

    __nv_bfloat16 *hhi,*hlo,*phi,*plo,*wihi,*wilo,*wbhi,*wblo; float* tot;
    cudaGetSymbolAddress((void**)&hhi,g_hhi);   cudaGetSymbolAddress((void**)&hlo,g_hlo);
    cudaGetSymbolAddress((void**)&phi,g_phi);   cudaGetSymbolAddress((void**)&plo,g_plo);
    cudaGetSymbolAddress((void**)&wihi,g_wihi); cudaGetSymbolAddress((void**)&wilo,g_wilo);
    cudaGetSymbolAddress((void**)&wbhi,g_wbhi); cudaGetSymbolAddress((void**)&wblo,g_wblo);
    cudaGetSymbolAddress((void**)&tot,g_tot);

    cudaFuncSetAttribute(gemm_bf16x3, cudaFuncAttributeMaxDynamicSharedMemorySize, SMEM_DYN);

    const size_t WI=(size_t)HDIM*KP;
    transpose_split<<<dim3(KP/32,HDIM/32,LEVELS),dim3(32,8)>>>(Win_f,96,HDIM,KP,wihi,wilo);
    transpose_split<<<dim3(KP/32,HDIM/32,LEVELS),dim3(32,8)>>>(Win_b,96,HDIM,KP,wihi+17*WI,wilo+17*WI);
    transpose_split<<<dim3(HDIM/32,HDIM/32,HS),dim3(32,8)>>>(Wblk,HDIM,HDIM,HDIM,wbhi,wblo);
    init_prev_k<<<(BATCH*KP+255)/256,256>>>(x,phi,plo);

    dim3 gg(HDIM/128, BATCH/128, 2);  // (8, 32, 2)
    const size_t PK=(size_t)BATCH*KP, WB=(size_t)HDIM*HDIM;
    for(int i=0;i<LEVELS;++i){
        gemm_bf16x3<<<gg,256,SMEM_DYN>>>(phi,plo,phi+PK,plo+PK,KP,
            wihi+(size_t)i*WI, wilo+(size_t)i*WI, wihi+(size_t)(17+i)*WI, wilo+(size_t)(17+i)*WI,
            bin_f+i*HDIM, bin_b+i*HDIM,
            hhi, hlo, hhi+2ull*HN, hlo+2ull*HN, KP, 0);
        int cur=0;
        for(int j=0;j<HS;++j){
            gemm_bf16x3<<<gg,256,SMEM_DYN>>>(
                hhi+(size_t)cur*HN, hlo+(size_t)cur*HN, hhi+(size_t)(2+cur)*HN, hlo+(size_t)(2+cur)*HN, HDIM,
                wbhi+(size_t)j*WB, wblo+(size_t)j*WB, wbhi+(size_t)j*WB, wblo+(size_t)j*WB,
                bblk+j*HDIM, bblk+j*HDIM,
                hhi+(size_t)(cur^1)*HN, hlo+(size_t)(cur^1)*HN,
                hhi+(size_t)(2+(cur^1))*HN, hlo+(size_t)(2+(cur^1))*HN, HDIM, 1);
            cur^=1;
        }
        out_proj<<<dim3(BATCH,1,2),256>>>(hhi,hlo,1,3,
            Wout_f+(size_t)i*HDIM*ODIM, Wout_b+(size_t)i*HDIM*ODIM,
            bout_f+i*ODIM, bout_b+i*ODIM, tot, phi, plo, i);
    }
    attn_final<<<BATCH,128>>>(tot,W1,W2,W3,W4,b4,out);
}

// round 8
// speedup vs baseline: 2.8051x; 1.0236x over previous
#include <cuda_runtime.h>
#include <cuda_bf16.h>
#include <cstdint>

#define BATCH 4096
#define IN_DIM 16
#define LEVELS 17
#define ODIM 5
#define HDIM 1024
#define HS 3
#define KP 128
#define TOTW (ODIM*LEVELS)
#define HN (BATCH*HDIM)

// ---------------- scratch ----------------
__device__ __nv_bfloat16 g_hhi[4ull*HN], g_hlo[4ull*HN];
__device__ __nv_bfloat16 g_phi[2ull*BATCH*KP], g_plo[2ull*BATCH*KP];
__device__ __nv_bfloat16 g_wihi[34ull*HDIM*KP], g_wilo[34ull*HDIM*KP];
__device__ __nv_bfloat16 g_wbhi[3ull*HDIM*HDIM], g_wblo[3ull*HDIM*HDIM];
__device__ float g_tot[2ull*BATCH*TOTW];

// ---------------- helpers ----------------
__device__ __forceinline__ uint32_t smem_u32(const void* p){ return (uint32_t)__cvta_generic_to_shared(p); }
__device__ __forceinline__ void cpa16(uint32_t d, const void* s){
    asm volatile("cp.async.cg.shared.global [%0], [%1], 16;" :: "r"(d),"l"(s)); }
#define CP_COMMIT() asm volatile("cp.async.commit_group;" ::: "memory")

__device__ __forceinline__ void ldsm4(uint32_t* r, uint32_t a){
    asm volatile("ldmatrix.sync.aligned.m8n8.x4.shared.b16 {%0,%1,%2,%3}, [%4];"
        : "=r"(r[0]),"=r"(r[1]),"=r"(r[2]),"=r"(r[3]) : "r"(a));
}
__device__ __forceinline__ void mma16816(float* d, const uint32_t* a, const uint32_t* b){
    asm volatile("mma.sync.aligned.m16n8k16.row.col.f32.bf16.bf16.f32 "
        "{%0,%1,%2,%3}, {%4,%5,%6,%7}, {%8,%9}, {%0,%1,%2,%3};"
        : "+f"(d[0]),"+f"(d[1]),"+f"(d[2]),"+f"(d[3])
        : "r"(a[0]),"r"(a[1]),"r"(a[2]),"r"(a[3]), "r"(b[0]),"r"(b[1]));
}

// ---------------- GEMM: C[4096xHDIM] = act(A @ B^T + bias), bf16x3 via mma.sync ----------------
// A[4096,AKD] hi/lo row-major; B[HDIM,AKD] hi/lo (pre-transposed, same K stride).
// 128x128 CTA tile, BK=32, 3-stage cp.async ring, 2 CTAs/SM. blockIdx.z = direction.
// Stage-wide B-fragment hoist + register double-buffered A fragments.
#define STG_SZ 32768   // Ahi 8K | Alo 8K | Bhi 8K | Blo 8K
#define SMEM_DYN (3*STG_SZ)

__global__ void __launch_bounds__(256, 2)
gemm_bf16x3(const __nv_bfloat16* __restrict__ Ah0, const __nv_bfloat16* __restrict__ Al0,
            const __nv_bfloat16* __restrict__ Ah1, const __nv_bfloat16* __restrict__ Al1, int AKD,
            const __nv_bfloat16* __restrict__ Bh0, const __nv_bfloat16* __restrict__ Bl0,
            const __nv_bfloat16* __restrict__ Bh1, const __nv_bfloat16* __restrict__ Bl1,
            const float* __restrict__ bias0, const float* __restrict__ bias1,
            __nv_bfloat16* __restrict__ oH0, __nv_bfloat16* __restrict__ oL0,
            __nv_bfloat16* __restrict__ oH1, __nv_bfloat16* __restrict__ oL1,
            int K, int relu)
{
    extern __shared__ char smem[];
    __shared__ float sbias[128];
    const int tid=threadIdx.x, wid=tid>>5, lane=tid&31, dir=blockIdx.z;
    const int Nbase=blockIdx.x*128, Mbase=blockIdx.y*128;
    const int warpM=wid&1, warpN=wid>>1;

    const __nv_bfloat16* Ah = dir?Ah1:Ah0; const __nv_bfloat16* Al = dir?Al1:Al0;
    const __nv_bfloat16* Bh = dir?Bh1:Bh0; const __nv_bfloat16* Bl = dir?Bl1:Bl0;
    const float* bias = dir?bias1:bias0;
    __nv_bfloat16* oH = dir?oH1:oH0; __nv_bfloat16* oL = dir?oL1:oL0;

    if(tid<128) sbias[tid]=bias[Nbase+tid];
    const uint32_t sbase=smem_u32(smem);

    // per-stage loader: 512 16B-chunks per sub-buffer, 2 per thread
    auto load_stage=[&](int s){
        const uint32_t sb = sbase + (uint32_t)(s%3)*STG_SZ;
        const int kb = s*32;
        #pragma unroll
        for(int i=0;i<2;++i){
            int idx = tid + i*256;          // 0..511
            int r = idx>>2, c = idx&3;
            uint32_t dst = sb + (uint32_t)(r*64 + ((c ^ ((r>>1)&3))*16));
            size_t ga = (size_t)(Mbase+r)*AKD + kb + c*8;
            size_t gb = (size_t)(Nbase+r)*AKD + kb + c*8;
            cpa16(dst,         Ah+ga);
            cpa16(dst+8192,    Al+ga);
            cpa16(dst+16384,   Bh+gb);
            cpa16(dst+24576,   Bl+gb);
        }
        CP_COMMIT();
    };

    float acc[4][4][4];
    #pragma unroll
    for(int m=0;m<4;++m)
        #pragma unroll
        for(int n=0;n<4;++n)
            #pragma unroll
            for(int i=0;i<4;++i) acc[m][n][i]=0.f;

    const int NS = K>>5;          // K/32, always >= 4 here
    load_stage(0); load_stage(1);

    for(int s=0;s<NS;++s){
        if(s+1<NS) asm volatile("cp.async.wait_group 1;":::"memory");
        else       asm volatile("cp.async.wait_group 0;":::"memory");
        __syncthreads();
        if(s+2<NS) load_stage(s+2);

        const uint32_t sb = sbase + (uint32_t)(s%3)*STG_SZ;

        // ---- hoist ALL B fragments for this stage (both k16 slices, hi+lo) ----
        uint32_t bf[2][2][4][2];   // [ks][hi/lo][ntile][2]
        #pragma unroll
        for(int ks=0;ks<2;++ks){
            #pragma unroll
            for(int ntp=0;ntp<2;++ntp){
                int grp = lane>>3;
                int tile = ntp*2 + (grp>>1);
                int n = warpN*32 + tile*8 + (lane&7);
                int cc = (ks*2 + (grp&1)) ^ ((n>>1)&3);
                uint32_t ad = sb + 16384u + (uint32_t)(n*64 + cc*16);
                uint32_t t[4];
                ldsm4(t, ad);
                bf[ks][0][2*ntp][0]=t[0]; bf[ks][0][2*ntp][1]=t[1];
                bf[ks][0][2*ntp+1][0]=t[2]; bf[ks][0][2*ntp+1][1]=t[3];
                ldsm4(t, ad + 8192);
                bf[ks][1][2*ntp][0]=t[0]; bf[ks][1][2*ntp][1]=t[1];
                bf[ks][1][2*ntp+1][0]=t[2]; bf[ks][1][2*ntp+1][1]=t[3];
            }
        }

        // ---- A fragments: register double-buffer over 8 (ks,mt) steps ----
        auto ldA=[&](int idx, uint32_t* a0, uint32_t* a1){
            int ks = idx>>2, mt = idx&3;
            int r = warpM*64 + mt*16 + (lane&15);
            int cc = (ks*2 + (lane>>4)) ^ ((r>>1)&3);
            uint32_t ad = sb + (uint32_t)(r*64 + cc*16);
            ldsm4(a0, ad);
            ldsm4(a1, ad + 8192);
        };

        uint32_t Abuf[2][2][4];    // [buf][hi/lo][4]
        ldA(0, Abuf[0][0], Abuf[0][1]);
        #pragma unroll
        for(int idx=0; idx<8; ++idx){
            int ks = idx>>2, mt = idx&3;
            int cur = idx&1, nx = cur^1;
            if(idx<7) ldA(idx+1, Abuf[nx][0], Abuf[nx][1]);
            #pragma unroll
            for(int nt=0;nt<4;++nt){
                mma16816(acc[mt][nt], Abuf[cur][0], bf[ks][0][nt]);  // hi*hi
                mma16816(acc[mt][nt], Abuf[cur][0], bf[ks][1][nt]);  // hi*lo
                mma16816(acc[mt][nt], Abuf[cur][1], bf[ks][0][nt]);  // lo*hi
            }
        }
    }

    // epilogue: bias + relu, hi/lo split, direct stores
    #pragma unroll
    for(int mt=0;mt<4;++mt){
        #pragma unroll
        for(int nt=0;nt<4;++nt){
            int rl = warpM*64 + mt*16 + (lane>>2);
            int cl = warpN*32 + nt*8 + (lane&3)*2;
            #pragma unroll
            for(int h=0;h<2;++h){
                int row = Mbase + rl + h*8;
                float v0 = acc[mt][nt][2*h]   + sbias[cl];
                float v1 = acc[mt][nt][2*h+1] + sbias[cl+1];
                if(relu){ v0=fmaxf(v0,0.f); v1=fmaxf(v1,0.f); }
                __nv_bfloat16 h0=__float2bfloat16(v0), h1=__float2bfloat16(v1);
                __nv_bfloat162 hv; hv.x=h0; hv.y=h1;
                __nv_bfloat162 lv; lv.x=__float2bfloat16(v0-__bfloat162float(h0));
                                   lv.y=__float2bfloat16(v1-__bfloat162float(h1));
                size_t o = (size_t)row*HDIM + Nbase + cl;
                *reinterpret_cast<uint32_t*>(oH+o) = *reinterpret_cast<uint32_t*>(&hv);
                *reinterpret_cast<uint32_t*>(oL+o) = *reinterpret_cast<uint32_t*>(&lv);
            }
        }
    }
}

// ---------------- transpose + hi/lo split: dst[n][k]=split(src[k][n]), k>=KD -> 0 ----------------
__global__ void transpose_split(const float* __restrict__ src, int KD, int ND, int KOUT,
                                __nv_bfloat16* __restrict__ dH, __nv_bfloat16* __restrict__ dL)
{
    __shared__ float t[32][33];
    const int mz=blockIdx.z;
    src+=(size_t)mz*KD*ND; dH+=(size_t)mz*ND*KOUT; dL+=(size_t)mz*ND*KOUT;
    const int kt=blockIdx.x*32, nt=blockIdx.y*32, tx=threadIdx.x, ty=threadIdx.y;
    for(int r=ty;r<32;r+=8){ int k=kt+r; t[r][tx]=(k<KD)?src[(size_t)k*ND+nt+tx]:0.f; }
    __syncthreads();
    for(int r=ty;r<32;r+=8){ int n=nt+r, k=kt+tx;
        float v=t[tx][r]; __nv_bfloat16 h=__float2bfloat16(v);
        dH[(size_t)n*KOUT+k]=h; dL[(size_t)n*KOUT+k]=__float2bfloat16(v-__bfloat162float(h)); }
}

// ---------------- init prev ----------------
__global__ void init_prev_k(const float* __restrict__ x,
                            __nv_bfloat16* __restrict__ phi, __nv_bfloat16* __restrict__ plo)
{
    int i=blockIdx.x*256+threadIdx.x; if(i>=BATCH*KP) return;
    int b=i>>7, c=i&127;
    float v=(c<IN_DIM)?x[b*IN_DIM+c]:0.f;
    __nv_bfloat16 h=__float2bfloat16(v);
    __nv_bfloat16 l=__float2bfloat16(v-__bfloat162float(h));
    size_t o2=(size_t)BATCH*KP;
    phi[i]=h; plo[i]=l; phi[i+o2]=h; plo[i+o2]=l;
}

// ---------------- out-proj ----------------
__global__ void out_proj(const __nv_bfloat16* __restrict__ hHi, const __nv_bfloat16* __restrict__ hLo,
                         int hi0, int hi1,
                         const float* __restrict__ Wf, const float* __restrict__ Wb,
                         const float* __restrict__ bf, const float* __restrict__ bb,
                         float* __restrict__ totbuf,
                         __nv_bfloat16* __restrict__ phi, __nv_bfloat16* __restrict__ plo,
                         int level)
{
    const int b=blockIdx.x, dir=blockIdx.z, tid=threadIdx.x;
    const size_t hoff=(size_t)(dir?hi1:hi0)*HN + (size_t)b*HDIM;
    const float* Wout = dir?Wb:Wf; const float* bout = dir?bb:bf;
    float* tot = totbuf + (size_t)dir*BATCH*TOTW;
    __nv_bfloat16* ph = phi + (size_t)dir*BATCH*KP;
    __nv_bfloat16* pl = plo + (size_t)dir*BATCH*KP;

    __shared__ float sh[HDIM];
    #pragma unroll
    for(int q=0;q<4;++q){ int k=tid+q*256;
        sh[k]=__bfloat162float(hHi[hoff+k])+__bfloat162float(hLo[hoff+k]); }
    __syncthreads();
    const int warp=tid>>5, lane=tid&31;
    if(warp<ODIM){
        float acc=0.f;
        for(int k=lane;k<HDIM;k+=32) acc+=sh[k]*Wout[k*ODIM+warp];
        #pragma unroll
        for(int off=16;off>0;off>>=1) acc+=__shfl_down_sync(0xffffffffu,acc,off);
        if(lane==0){
            float val=acc+bout[warp];
            tot[b*TOTW+level*ODIM+warp]=val;
            if(level<LEVELS-1){
                int pc=b*KP+IN_DIM+level*ODIM+warp;
                __nv_bfloat16 h=__float2bfloat16(val);
                ph[pc]=h; pl[pc]=__float2bfloat16(val-__bfloat162float(h));
            }
        }
    }
}

// ---------------- attention + final linear ----------------
__global__ void attn_final(const float* __restrict__ totbuf,
                           const float* __restrict__ W1, const float* __restrict__ W2,
                           const float* __restrict__ W3, const float* __restrict__ W4,
                           const float* __restrict__ b4, float* __restrict__ out)
{
    const int b=blockIdx.x;
    const float* totF=totbuf; const float* totB=totbuf+(size_t)BATCH*TOTW;
    __shared__ float tf[ODIM][LEVELS], tb[ODIM][LEVELS];
    __shared__ float q[LEVELS][ODIM], kk[ODIM][LEVELS], v[LEVELS][ODIM];
    __shared__ float attn[LEVELS][LEVELS], res[TOTW], w1[25], w2[25], w3[25];
    const int tid=threadIdx.x;
    if(tid<TOTW){
        reinterpret_cast<float*>(tf)[tid]=totF[b*TOTW+tid];
        int d=tid/LEVELS, t=tid%LEVELS;
        tb[d][t]=totB[b*TOTW+d*LEVELS+(LEVELS-1-t)];
    }
    if(tid<25){ w1[tid]=W1[tid]; w2[tid]=W2[tid]; w3[tid]=W3[tid]; }
    __syncthreads();
    if(tid<TOTW){
        int t=tid/ODIM, e=tid%ODIM;
        float sq=0.f,sk=0.f,sv=0.f;
        #pragma unroll
        for(int d=0;d<ODIM;++d){
            sq+=tf[d][t]*w1[d*ODIM+e]; sk+=tb[d][t]*w2[d*ODIM+e]; sv+=tb[d][t]*w3[d*ODIM+e]; }
        q[t][e]=sq; kk[e][t]=sk; v[t][e]=sv;
    }
    __syncthreads();
    for(int idx=tid;idx<LEVELS*LEVELS;idx+=blockDim.x){
        int t=idx/LEVELS, s=idx%LEVELS;
        float sc=0.f;
        #pragma unroll
        for(int e=0;e<ODIM;++e) sc+=q[t][e]*kk[e][s];
        attn[t][s]=sc;
    }
    __syncthreads();
    if(tid<LEVELS){
        int s=tid; float mx=-1e30f;
        for(int t=0;t<LEVELS;++t) mx=fmaxf(mx,attn[t][s]);
        float sm=0.f;
        for(int t=0;t<LEVELS;++t){ float e=expf(attn[t][s]-mx); attn[t][s]=e; sm+=e; }
        float inv=1.f/sm;
        for(int t=0;t<LEVELS;++t) attn[t][s]*=inv;
    }
    __syncthreads();
    if(tid<TOTW){
        int t=tid/ODIM, e=tid%ODIM; float r=0.f;
        for(int s=0;s<LEVELS;++s) r+=attn[t][s]*v[s][e];
        res[tid]=r;
    }
    __syncthreads();
    if(tid<TOTW){
        int o=tid; float y=b4[o];
        for(int j=0;j<TOTW;++j) y+=res[j]*W4[j*TOTW+o];
        out[(size_t)b*TOTW+o]=y;
    }
}

// ---------------- host ----------------
extern "C" void kernel_launch(void* const* d_in, const int* in_sizes, int n_in,
                              void* d_out, int out_size)
{
    const float* x=(const float*)d_in[0];
    const float* Win_f=(const float*)d_in[1];  const float* bin_f=(const float*)d_in[2];
    const float* Win_b=(const float*)d_in[3];  const float* bin_b=(const float*)d_in[4];
    const float* Wblk=(const float*)d_in[5];   const float* bblk=(const float*)d_in[6];
    const float* Wout_f=(const float*)d_in[7]; const float* bout_f=(const float*)d_in[8];
    const float* Wout_b=(const float*)d_in[9]; const float* bout_b=(const float*)d_in[10];
    const float* W1=(const float*)d_in[11]; const float* W2=(const float*)d_in[12];
    const float* W3=(const float*)d_in[13]; const float* W4=(const float*)d_in[14];
    const float* b4=(const float*)d_in[15];
    float* out=(float*)d_out;

    __nv_bfloat16 *hhi,*hlo,*phi,*plo,*wihi,*wilo,*wbhi,*wblo; float* tot;
    cudaGetSymbolAddress((void**)&hhi,g_hhi);   cudaGetSymbolAddress((void**)&hlo,g_hlo);
    cudaGetSymbolAddress((void**)&phi,g_phi);   cudaGetSymbolAddress((void**)&plo,g_plo);
    cudaGetSymbolAddress((void**)&wihi,g_wihi); cudaGetSymbolAddress((void**)&wilo,g_wilo);
    cudaGetSymbolAddress((void**)&wbhi,g_wbhi); cudaGetSymbolAddress((void**)&wblo,g_wblo);
    cudaGetSymbolAddress((void**)&tot,g_tot);

    cudaFuncSetAttribute(gemm_bf16x3, cudaFuncAttributeMaxDynamicSharedMemorySize, SMEM_DYN);

    const size_t WI=(size_t)HDIM*KP;
    transpose_split<<<dim3(KP/32,HDIM/32,LEVELS),dim3(32,8)>>>(Win_f,96,HDIM,KP,wihi,wilo);
    transpose_split<<<dim3(KP/32,HDIM/32,LEVELS),dim3(32,8)>>>(Win_b,96,HDIM,KP,wihi+17*WI,wilo+17*WI);
    transpose_split<<<dim3(HDIM/32,HDIM/32,HS),dim3(32,8)>>>(Wblk,HDIM,HDIM,HDIM,wbhi,wblo);
    init_prev_k<<<(BATCH*KP+255)/256,256>>>(x,phi,plo);

    dim3 gg(HDIM/128, BATCH/128, 2);  // (8, 32, 2)
    const size_t PK=(size_t)BATCH*KP, WB=(size_t)HDIM*HDIM;
    for(int i=0;i<LEVELS;++i){
        gemm_bf16x3<<<gg,256,SMEM_DYN>>>(phi,plo,phi+PK,plo+PK,KP,
            wihi+(size_t)i*WI, wilo+(size_t)i*WI, wihi+(size_t)(17+i)*WI, wilo+(size_t)(17+i)*WI,
            bin_f+i*HDIM, bin_b+i*HDIM,
            hhi, hlo, hhi+2ull*HN, hlo+2ull*HN, KP, 0);
        int cur=0;
        for(int j=0;j<HS;++j){
            gemm_bf16x3<<<gg,256,SMEM_DYN>>>(
                hhi+(size_t)cur*HN, hlo+(size_t)cur*HN, hhi+(size_t)(2+cur)*HN, hlo+(size_t)(2+cur)*HN, HDIM,
                wbhi+(size_t)j*WB, wblo+(size_t)j*WB, wbhi+(size_t)j*WB, wblo+(size_t)j*WB,
                bblk+j*HDIM, bblk+j*HDIM,
                hhi+(size_t)(cur^1)*HN, hlo+(size_t)(cur^1)*HN,
                hhi+(size_t)(2+(cur^1))*HN, hlo+(size_t)(2+(cur^1))*HN, HDIM, 1);
            cur^=1;
        }
        out_proj<<<dim3(BATCH,1,2),256>>>(hhi,hlo,1,3,
            Wout_f+(size_t)i*HDIM*ODIM, Wout_b+(size_t)i*HDIM*ODIM,
            bout_f+i*ODIM, bout_b+i*ODIM, tot, phi, plo, i);
    }
    attn_final<<<BATCH,128>>>(tot,W1,W2,W3,W4,b4,out);
}

// round 9
// speedup vs baseline: 2.8090x; 1.0014x over previous
#include <cuda_runtime.h>
#include <cuda_bf16.h>
#include <cstdint>

#define BATCH 4096
#define IN_DIM 16
#define LEVELS 17
#define ODIM 5
#define HDIM 1024
#define HS 3
#define KP 128
#define TOTW (ODIM*LEVELS)
#define HN (BATCH*HDIM)

// ---------------- scratch ----------------
__device__ __nv_bfloat16 g_hhi[4ull*HN], g_hlo[4ull*HN];
__device__ __nv_bfloat16 g_phi[2ull*BATCH*KP], g_plo[2ull*BATCH*KP];
__device__ __nv_bfloat16 g_wihi[34ull*HDIM*KP], g_wilo[34ull*HDIM*KP];
__device__ __nv_bfloat16 g_wbhi[3ull*HDIM*HDIM], g_wblo[3ull*HDIM*HDIM];
__device__ float g_tot[2ull*BATCH*TOTW];

// ---------------- helpers ----------------
__device__ __forceinline__ uint32_t smem_u32(const void* p){ return (uint32_t)__cvta_generic_to_shared(p); }
__device__ __forceinline__ void cpa16(uint32_t d, const void* s){
    asm volatile("cp.async.cg.shared.global [%0], [%1], 16;" :: "r"(d),"l"(s)); }
#define CP_COMMIT() asm volatile("cp.async.commit_group;" ::: "memory")

__device__ __forceinline__ void ldsm4(uint32_t* r, uint32_t a){
    asm volatile("ldmatrix.sync.aligned.m8n8.x4.shared.b16 {%0,%1,%2,%3}, [%4];"
        : "=r"(r[0]),"=r"(r[1]),"=r"(r[2]),"=r"(r[3]) : "r"(a));
}
// NOTE: non-volatile on purpose — pure register dataflow, lets nvcc/ptxas
// interleave independent MMAs to hide HMMA latency.
__device__ __forceinline__ void mma16816(float* d, const uint32_t* a, const uint32_t* b){
    asm("mma.sync.aligned.m16n8k16.row.col.f32.bf16.bf16.f32 "
        "{%0,%1,%2,%3}, {%4,%5,%6,%7}, {%8,%9}, {%0,%1,%2,%3};"
        : "+f"(d[0]),"+f"(d[1]),"+f"(d[2]),"+f"(d[3])
        : "r"(a[0]),"r"(a[1]),"r"(a[2]),"r"(a[3]), "r"(b[0]),"r"(b[1]));
}

// ---------------- GEMM: C[4096xHDIM] = act(A @ B^T + bias), bf16x3 via mma.sync ----------------
// A[4096,AKD] hi/lo row-major; B[HDIM,AKD] hi/lo (pre-transposed, same K stride).
// 128x128 CTA tile, BK=32, 3-stage cp.async ring, 2 CTAs/SM. blockIdx.z = direction.
// Stage-wide B-fragment hoist + reg double-buffered A + pass-major MMA ordering.
#define STG_SZ 32768   // Ahi 8K | Alo 8K | Bhi 8K | Blo 8K
#define SMEM_DYN (3*STG_SZ)

__global__ void __launch_bounds__(256, 2)
gemm_bf16x3(const __nv_bfloat16* __restrict__ Ah0, const __nv_bfloat16* __restrict__ Al0,
            const __nv_bfloat16* __restrict__ Ah1, const __nv_bfloat16* __restrict__ Al1, int AKD,
            const __nv_bfloat16* __restrict__ Bh0, const __nv_bfloat16* __restrict__ Bl0,
            const __nv_bfloat16* __restrict__ Bh1, const __nv_bfloat16* __restrict__ Bl1,
            const float* __restrict__ bias0, const float* __restrict__ bias1,
            __nv_bfloat16* __restrict__ oH0, __nv_bfloat16* __restrict__ oL0,
            __nv_bfloat16* __restrict__ oH1, __nv_bfloat16* __restrict__ oL1,
            int K, int relu)
{
    extern __shared__ char smem[];
    __shared__ float sbias[128];
    const int tid=threadIdx.x, wid=tid>>5, lane=tid&31, dir=blockIdx.z;
    const int Nbase=blockIdx.x*128, Mbase=blockIdx.y*128;
    const int warpM=wid&1, warpN=wid>>1;

    const __nv_bfloat16* Ah = dir?Ah1:Ah0; const __nv_bfloat16* Al = dir?Al1:Al0;
    const __nv_bfloat16* Bh = dir?Bh1:Bh0; const __nv_bfloat16* Bl = dir?Bl1:Bl0;
    const float* bias = dir?bias1:bias0;
    __nv_bfloat16* oH = dir?oH1:oH0; __nv_bfloat16* oL = dir?oL1:oL0;

    if(tid<128) sbias[tid]=bias[Nbase+tid];
    const uint32_t sbase=smem_u32(smem);

    // per-stage loader: 512 16B-chunks per sub-buffer, 2 per thread
    auto load_stage=[&](int s){
        const uint32_t sb = sbase + (uint32_t)(s%3)*STG_SZ;
        const int kb = s*32;
        #pragma unroll
        for(int i=0;i<2;++i){
            int idx = tid + i*256;          // 0..511
            int r = idx>>2, c = idx&3;
            uint32_t dst = sb + (uint32_t)(r*64 + ((c ^ ((r>>1)&3))*16));
            size_t ga = (size_t)(Mbase+r)*AKD + kb + c*8;
            size_t gb = (size_t)(Nbase+r)*AKD + kb + c*8;
            cpa16(dst,         Ah+ga);
            cpa16(dst+8192,    Al+ga);
            cpa16(dst+16384,   Bh+gb);
            cpa16(dst+24576,   Bl+gb);
        }
        CP_COMMIT();
    };

    float acc[4][4][4];
    #pragma unroll
    for(int m=0;m<4;++m)
        #pragma unroll
        for(int n=0;n<4;++n)
            #pragma unroll
            for(int i=0;i<4;++i) acc[m][n][i]=0.f;

    const int NS = K>>5;          // K/32, always >= 4 here
    load_stage(0); load_stage(1);

    for(int s=0;s<NS;++s){
        if(s+1<NS) asm volatile("cp.async.wait_group 1;":::"memory");
        else       asm volatile("cp.async.wait_group 0;":::"memory");
        __syncthreads();
        if(s+2<NS) load_stage(s+2);

        const uint32_t sb = sbase + (uint32_t)(s%3)*STG_SZ;

        // ---- hoist ALL B fragments for this stage (both k16 slices, hi+lo) ----
        uint32_t bf[2][2][4][2];   // [ks][hi/lo][ntile][2]
        #pragma unroll
        for(int ks=0;ks<2;++ks){
            #pragma unroll
            for(int ntp=0;ntp<2;++ntp){
                int grp = lane>>3;
                int tile = ntp*2 + (grp>>1);
                int n = warpN*32 + tile*8 + (lane&7);
                int cc = (ks*2 + (grp&1)) ^ ((n>>1)&3);
                uint32_t ad = sb + 16384u + (uint32_t)(n*64 + cc*16);
                uint32_t t[4];
                ldsm4(t, ad);
                bf[ks][0][2*ntp][0]=t[0]; bf[ks][0][2*ntp][1]=t[1];
                bf[ks][0][2*ntp+1][0]=t[2]; bf[ks][0][2*ntp+1][1]=t[3];
                ldsm4(t, ad + 8192);
                bf[ks][1][2*ntp][0]=t[0]; bf[ks][1][2*ntp][1]=t[1];
                bf[ks][1][2*ntp+1][0]=t[2]; bf[ks][1][2*ntp+1][1]=t[3];
            }
        }

        // ---- A fragments: register double-buffer over 8 (ks,mt) steps ----
        auto ldA=[&](int idx, uint32_t* a0, uint32_t* a1){
            int ks = idx>>2, mt = idx&3;
            int r = warpM*64 + mt*16 + (lane&15);
            int cc = (ks*2 + (lane>>4)) ^ ((r>>1)&3);
            uint32_t ad = sb + (uint32_t)(r*64 + cc*16);
            ldsm4(a0, ad);
            ldsm4(a1, ad + 8192);
        };

        uint32_t Abuf[2][2][4];    // [buf][hi/lo][4]
        ldA(0, Abuf[0][0], Abuf[0][1]);
        #pragma unroll
        for(int idx=0; idx<8; ++idx){
            int ks = idx>>2, mt = idx&3;
            int cur = idx&1, nx = cur^1;
            if(idx<7) ldA(idx+1, Abuf[nx][0], Abuf[nx][1]);
            // pass-major ordering: dependent MMAs on the same acc are 4 apart
            #pragma unroll
            for(int nt=0;nt<4;++nt) mma16816(acc[mt][nt], Abuf[cur][0], bf[ks][0][nt]); // hi*hi
            #pragma unroll
            for(int nt=0;nt<4;++nt) mma16816(acc[mt][nt], Abuf[cur][0], bf[ks][1][nt]); // hi*lo
            #pragma unroll
            for(int nt=0;nt<4;++nt) mma16816(acc[mt][nt], Abuf[cur][1], bf[ks][0][nt]); // lo*hi
        }
    }

    // epilogue: bias + relu, hi/lo split, direct stores
    #pragma unroll
    for(int mt=0;mt<4;++mt){
        #pragma unroll
        for(int nt=0;nt<4;++nt){
            int rl = warpM*64 + mt*16 + (lane>>2);
            int cl = warpN*32 + nt*8 + (lane&3)*2;
            #pragma unroll
            for(int h=0;h<2;++h){
                int row = Mbase + rl + h*8;
                float v0 = acc[mt][nt][2*h]   + sbias[cl];
                float v1 = acc[mt][nt][2*h+1] + sbias[cl+1];
                if(relu){ v0=fmaxf(v0,0.f); v1=fmaxf(v1,0.f); }
                __nv_bfloat16 h0=__float2bfloat16(v0), h1=__float2bfloat16(v1);
                __nv_bfloat162 hv; hv.x=h0; hv.y=h1;
                __nv_bfloat162 lv; lv.x=__float2bfloat16(v0-__bfloat162float(h0));
                                   lv.y=__float2bfloat16(v1-__bfloat162float(h1));
                size_t o = (size_t)row*HDIM + Nbase + cl;
                *reinterpret_cast<uint32_t*>(oH+o) = *reinterpret_cast<uint32_t*>(&hv);
                *reinterpret_cast<uint32_t*>(oL+o) = *reinterpret_cast<uint32_t*>(&lv);
            }
        }
    }
}

// ---------------- transpose + hi/lo split: dst[n][k]=split(src[k][n]), k>=KD -> 0 ----------------
__global__ void transpose_split(const float* __restrict__ src, int KD, int ND, int KOUT,
                                __nv_bfloat16* __restrict__ dH, __nv_bfloat16* __restrict__ dL)
{
    __shared__ float t[32][33];
    const int mz=blockIdx.z;
    src+=(size_t)mz*KD*ND; dH+=(size_t)mz*ND*KOUT; dL+=(size_t)mz*ND*KOUT;
    const int kt=blockIdx.x*32, nt=blockIdx.y*32, tx=threadIdx.x, ty=threadIdx.y;
    for(int r=ty;r<32;r+=8){ int k=kt+r; t[r][tx]=(k<KD)?src[(size_t)k*ND+nt+tx]:0.f; }
    __syncthreads();
    for(int r=ty;r<32;r+=8){ int n=nt+r, k=kt+tx;
        float v=t[tx][r]; __nv_bfloat16 h=__float2bfloat16(v);
        dH[(size_t)n*KOUT+k]=h; dL[(size_t)n*KOUT+k]=__float2bfloat16(v-__bfloat162float(h)); }
}

// ---------------- init prev ----------------
__global__ void init_prev_k(const float* __restrict__ x,
                            __nv_bfloat16* __restrict__ phi, __nv_bfloat16* __restrict__ plo)
{
    int i=blockIdx.x*256+threadIdx.x; if(i>=BATCH*KP) return;
    int b=i>>7, c=i&127;
    float v=(c<IN_DIM)?x[b*IN_DIM+c]:0.f;
    __nv_bfloat16 h=__float2bfloat16(v);
    __nv_bfloat16 l=__float2bfloat16(v-__bfloat162float(h));
    size_t o2=(size_t)BATCH*KP;
    phi[i]=h; plo[i]=l; phi[i+o2]=h; plo[i+o2]=l;
}

// ---------------- out-proj ----------------
__global__ void out_proj(const __nv_bfloat16* __restrict__ hHi, const __nv_bfloat16* __restrict__ hLo,
                         int hi0, int hi1,
                         const float* __restrict__ Wf, const float* __restrict__ Wb,
                         const float* __restrict__ bf, const float* __restrict__ bb,
                         float* __restrict__ totbuf,
                         __nv_bfloat16* __restrict__ phi, __nv_bfloat16* __restrict__ plo,
                         int level)
{
    const int b=blockIdx.x, dir=blockIdx.z, tid=threadIdx.x;
    const size_t hoff=(size_t)(dir?hi1:hi0)*HN + (size_t)b*HDIM;
    const float* Wout = dir?Wb:Wf; const float* bout = dir?bb:bf;
    float* tot = totbuf + (size_t)dir*BATCH*TOTW;
    __nv_bfloat16* ph = phi + (size_t)dir*BATCH*KP;
    __nv_bfloat16* pl = plo + (size_t)dir*BATCH*KP;

    __shared__ float sh[HDIM];
    #pragma unroll
    for(int q=0;q<4;++q){ int k=tid+q*256;
        sh[k]=__bfloat162float(hHi[hoff+k])+__bfloat162float(hLo[hoff+k]); }
    __syncthreads();
    const int warp=tid>>5, lane=tid&31;
    if(warp<ODIM){
        float acc=0.f;
        for(int k=lane;k<HDIM;k+=32) acc+=sh[k]*Wout[k*ODIM+warp];
        #pragma unroll
        for(int off=16;off>0;off>>=1) acc+=__shfl_down_sync(0xffffffffu,acc,off);
        if(lane==0){
            float val=acc+bout[warp];
            tot[b*TOTW+level*ODIM+warp]=val;
            if(level<LEVELS-1){
                int pc=b*KP+IN_DIM+level*ODIM+warp;
                __nv_bfloat16 h=__float2bfloat16(val);
                ph[pc]=h; pl[pc]=__float2bfloat16(val-__bfloat162float(h));
            }
        }
    }
}

// ---------------- attention + final linear ----------------
__global__ void attn_final(const float* __restrict__ totbuf,
                           const float* __restrict__ W1, const float* __restrict__ W2,
                           const float* __restrict__ W3, const float* __restrict__ W4,
                           const float* __restrict__ b4, float* __restrict__ out)
{
    const int b=blockIdx.x;
    const float* totF=totbuf; const float* totB=totbuf+(size_t)BATCH*TOTW;
    __shared__ float tf[ODIM][LEVELS], tb[ODIM][LEVELS];
    __shared__ float q[LEVELS][ODIM], kk[ODIM][LEVELS], v[LEVELS][ODIM];
    __shared__ float attn[LEVELS][LEVELS], res[TOTW], w1[25], w2[25], w3[25];
    const int tid=threadIdx.x;
    if(tid<TOTW){
        reinterpret_cast<float*>(tf)[tid]=totF[b*TOTW+tid];
        int d=tid/LEVELS, t=tid%LEVELS;
        tb[d][t]=totB[b*TOTW+d*LEVELS+(LEVELS-1-t)];
    }
    if(tid<25){ w1[tid]=W1[tid]; w2[tid]=W2[tid]; w3[tid]=W3[tid]; }
    __syncthreads();
    if(tid<TOTW){
        int t=tid/ODIM, e=tid%ODIM;
        float sq=0.f,sk=0.f,sv=0.f;
        #pragma unroll
        for(int d=0;d<ODIM;++d){
            sq+=tf[d][t]*w1[d*ODIM+e]; sk+=tb[d][t]*w2[d*ODIM+e]; sv+=tb[d][t]*w3[d*ODIM+e]; }
        q[t][e]=sq; kk[e][t]=sk; v[t][e]=sv;
    }
    __syncthreads();
    for(int idx=tid;idx<LEVELS*LEVELS;idx+=blockDim.x){
        int t=idx/LEVELS, s=idx%LEVELS;
        float sc=0.f;
        #pragma unroll
        for(int e=0;e<ODIM;++e) sc+=q[t][e]*kk[e][s];
        attn[t][s]=sc;
    }
    __syncthreads();
    if(tid<LEVELS){
        int s=tid; float mx=-1e30f;
        for(int t=0;t<LEVELS;++t) mx=fmaxf(mx,attn[t][s]);
        float sm=0.f;
        for(int t=0;t<LEVELS;++t){ float e=expf(attn[t][s]-mx); attn[t][s]=e; sm+=e; }
        float inv=1.f/sm;
        for(int t=0;t<LEVELS;++t) attn[t][s]*=inv;
    }
    __syncthreads();
    if(tid<TOTW){
        int t=tid/ODIM, e=tid%ODIM; float r=0.f;
        for(int s=0;s<LEVELS;++s) r+=attn[t][s]*v[s][e];
        res[tid]=r;
    }
    __syncthreads();
    if(tid<TOTW){
        int o=tid; float y=b4[o];
        for(int j=0;j<TOTW;++j) y+=res[j]*W4[j*TOTW+o];
        out[(size_t)b*TOTW+o]=y;
    }
}

// ---------------- host ----------------
extern "C" void kernel_launch(void* const* d_in, const int* in_sizes, int n_in,
                              void* d_out, int out_size)
{
    const float* x=(const float*)d_in[0];
    const float* Win_f=(const float*)d_in[1];  const float* bin_f=(const float*)d_in[2];
    const float* Win_b=(const float*)d_in[3];  const float* bin_b=(const float*)d_in[4];
    const float* Wblk=(const float*)d_in[5];   const float* bblk=(const float*)d_in[6];
    const float* Wout_f=(const float*)d_in[7]; const float* bout_f=(const float*)d_in[8];
    const float* Wout_b=(const float*)d_in[9]; const float* bout_b=(const float*)d_in[10];
    const float* W1=(const float*)d_in[11]; const float* W2=(const float*)d_in[12];
    const float* W3=(const float*)d_in[13]; const float* W4=(const float*)d_in[14];
    const float* b4=(const float*)d_in[15];
    float* out=(float*)d_out;

    __nv_bfloat16 *hhi,*hlo,*phi,*plo,*wihi,*wilo,*wbhi,*wblo; float* tot;
    cudaGetSymbolAddress((void**)&hhi,g_hhi);   cudaGetSymbolAddress((void**)&hlo,g_hlo);
    cudaGetSymbolAddress((void**)&phi,g_phi);   cudaGetSymbolAddress((void**)&plo,g_plo);
    cudaGetSymbolAddress((void**)&wihi,g_wihi); cudaGetSymbolAddress((void**)&wilo,g_wilo);
    cudaGetSymbolAddress((void**)&wbhi,g_wbhi); cudaGetSymbolAddress((void**)&wblo,g_wblo);
    cudaGetSymbolAddress((void**)&tot,g_tot);

    cudaFuncSetAttribute(gemm_bf16x3, cudaFuncAttributeMaxDynamicSharedMemorySize, SMEM_DYN);

    const size_t WI=(size_t)HDIM*KP;
    transpose_split<<<dim3(KP/32,HDIM/32,LEVELS),dim3(32,8)>>>(Win_f,96,HDIM,KP,wihi,wilo);
    transpose_split<<<dim3(KP/32,HDIM/32,LEVELS),dim3(32,8)>>>(Win_b,96,HDIM,KP,wihi+17*WI,wilo+17*WI);
    transpose_split<<<dim3(HDIM/32,HDIM/32,HS),dim3(32,8)>>>(Wblk,HDIM,HDIM,HDIM,wbhi,wblo);
    init_prev_k<<<(BATCH*KP+255)/256,256>>>(x,phi,plo);

    dim3 gg(HDIM/128, BATCH/128, 2);  // (8, 32, 2)
    const size_t PK=(size_t)BATCH*KP, WB=(size_t)HDIM*HDIM;
    for(int i=0;i<LEVELS;++i){
        gemm_bf16x3<<<gg,256,SMEM_DYN>>>(phi,plo,phi+PK,plo+PK,KP,
            wihi+(size_t)i*WI, wilo+(size_t)i*WI, wihi+(size_t)(17+i)*WI, wilo+(size_t)(17+i)*WI,
            bin_f+i*HDIM, bin_b+i*HDIM,
            hhi, hlo, hhi+2ull*HN, hlo+2ull*HN, KP, 0);
        int cur=0;
        for(int j=0;j<HS;++j){
            gemm_bf16x3<<<gg,256,SMEM_DYN>>>(
                hhi+(size_t)cur*HN, hlo+(size_t)cur*HN, hhi+(size_t)(2+cur)*HN, hlo+(size_t)(2+cur)*HN, HDIM,
                wbhi+(size_t)j*WB, wblo+(size_t)j*WB, wbhi+(size_t)j*WB, wblo+(size_t)j*WB,
                bblk+j*HDIM, bblk+j*HDIM,
                hhi+(size_t)(cur^1)*HN, hlo+(size_t)(cur^1)*HN,
                hhi+(size_t)(2+(cur^1))*HN, hlo+(size_t)(2+(cur^1))*HN, HDIM, 1);
            cur^=1;
        }
        out_proj<<<dim3(BATCH,1,2),256>>>(hhi,hlo,1,3,
            Wout_f+(size_t)i*HDIM*ODIM, Wout_b+(size_t)i*HDIM*ODIM,
            bout_f+i*ODIM, bout_b+i*ODIM, tot, phi, plo, i);
    }
    attn_final<<<BATCH,128>>>(tot,W1,W2,W3,W4,b4,out);
}

// round 10
// speedup vs baseline: 3.3605x; 1.1963x over previous
#include <cuda_runtime.h>
#include <cuda_bf16.h>
#include <cstdint>

#define BATCH 4096
#define IN_DIM 16
#define LEVELS 17
#define ODIM 5
#define HDIM 1024
#define HS 3
#define KP 128
#define TOTW (ODIM*LEVELS)
#define HN (BATCH*HDIM)

// ---------------- scratch ----------------
__device__ __nv_bfloat16 g_hhi[4ull*HN], g_hlo[4ull*HN];
__device__ __nv_bfloat16 g_phi[2ull*BATCH*KP], g_plo[2ull*BATCH*KP];
__device__ __nv_bfloat16 g_wihi[34ull*HDIM*KP], g_wilo[34ull*HDIM*KP];
__device__ __nv_bfloat16 g_wbhi[3ull*HDIM*HDIM], g_wblo[3ull*HDIM*HDIM];
__device__ float g_tot[2ull*BATCH*TOTW];

// ---------------- helpers ----------------
__device__ __forceinline__ uint32_t smem_u32(const void* p){ return (uint32_t)__cvta_generic_to_shared(p); }
__device__ __forceinline__ void cpa16(uint32_t d, const void* s){
    asm volatile("cp.async.cg.shared.global [%0], [%1], 16;" :: "r"(d),"l"(s)); }
#define CP_COMMIT() asm volatile("cp.async.commit_group;" ::: "memory")

__device__ __forceinline__ void ldsm4(uint32_t* r, uint32_t a){
    asm volatile("ldmatrix.sync.aligned.m8n8.x4.shared.b16 {%0,%1,%2,%3}, [%4];"
        : "=r"(r[0]),"=r"(r[1]),"=r"(r[2]),"=r"(r[3]) : "r"(a));
}
// non-volatile: pure register dataflow, lets ptxas interleave MMAs
__device__ __forceinline__ void mma16816(float* d, const uint32_t* a, const uint32_t* b){
    asm("mma.sync.aligned.m16n8k16.row.col.f32.bf16.bf16.f32 "
        "{%0,%1,%2,%3}, {%4,%5,%6,%7}, {%8,%9}, {%0,%1,%2,%3};"
        : "+f"(d[0]),"+f"(d[1]),"+f"(d[2]),"+f"(d[3])
        : "r"(a[0]),"r"(a[1]),"r"(a[2]),"r"(a[3]), "r"(b[0]),"r"(b[1]));
}

// ---------------- GEMM: C[4096xHDIM] = act(A @ B^T + bias), bf16x3 via mma.sync ----------------
// Launched per-direction with gridDim.z = 1 (dir = 0 -> slot-0 pointers).
#define STG_SZ 32768   // Ahi 8K | Alo 8K | Bhi 8K | Blo 8K
#define SMEM_DYN (3*STG_SZ)

__global__ void __launch_bounds__(256, 2)
gemm_bf16x3(const __nv_bfloat16* __restrict__ Ah0, const __nv_bfloat16* __restrict__ Al0,
            const __nv_bfloat16* __restrict__ Ah1, const __nv_bfloat16* __restrict__ Al1, int AKD,
            const __nv_bfloat16* __restrict__ Bh0, const __nv_bfloat16* __restrict__ Bl0,
            const __nv_bfloat16* __restrict__ Bh1, const __nv_bfloat16* __restrict__ Bl1,
            const float* __restrict__ bias0, const float* __restrict__ bias1,
            __nv_bfloat16* __restrict__ oH0, __nv_bfloat16* __restrict__ oL0,
            __nv_bfloat16* __restrict__ oH1, __nv_bfloat16* __restrict__ oL1,
            int K, int relu)
{
    extern __shared__ char smem[];
    __shared__ float sbias[128];
    const int tid=threadIdx.x, wid=tid>>5, lane=tid&31, dir=blockIdx.z;
    const int Nbase=blockIdx.x*128, Mbase=blockIdx.y*128;
    const int warpM=wid&1, warpN=wid>>1;

    const __nv_bfloat16* Ah = dir?Ah1:Ah0; const __nv_bfloat16* Al = dir?Al1:Al0;
    const __nv_bfloat16* Bh = dir?Bh1:Bh0; const __nv_bfloat16* Bl = dir?Bl1:Bl0;
    const float* bias = dir?bias1:bias0;
    __nv_bfloat16* oH = dir?oH1:oH0; __nv_bfloat16* oL = dir?oL1:oL0;

    if(tid<128) sbias[tid]=bias[Nbase+tid];
    const uint32_t sbase=smem_u32(smem);

    auto load_stage=[&](int s){
        const uint32_t sb = sbase + (uint32_t)(s%3)*STG_SZ;
        const int kb = s*32;
        #pragma unroll
        for(int i=0;i<2;++i){
            int idx = tid + i*256;
            int r = idx>>2, c = idx&3;
            uint32_t dst = sb + (uint32_t)(r*64 + ((c ^ ((r>>1)&3))*16));
            size_t ga = (size_t)(Mbase+r)*AKD + kb + c*8;
            size_t gb = (size_t)(Nbase+r)*AKD + kb + c*8;
            cpa16(dst,         Ah+ga);
            cpa16(dst+8192,    Al+ga);
            cpa16(dst+16384,   Bh+gb);
            cpa16(dst+24576,   Bl+gb);
        }
        CP_COMMIT();
    };

    float acc[4][4][4];
    #pragma unroll
    for(int m=0;m<4;++m)
        #pragma unroll
        for(int n=0;n<4;++n)
            #pragma unroll
            for(int i=0;i<4;++i) acc[m][n][i]=0.f;

    const int NS = K>>5;
    load_stage(0); load_stage(1);

    for(int s=0;s<NS;++s){
        if(s+1<NS) asm volatile("cp.async.wait_group 1;":::"memory");
        else       asm volatile("cp.async.wait_group 0;":::"memory");
        __syncthreads();
        if(s+2<NS) load_stage(s+2);

        const uint32_t sb = sbase + (uint32_t)(s%3)*STG_SZ;

        uint32_t bf[2][2][4][2];   // [ks][hi/lo][ntile][2]
        #pragma unroll
        for(int ks=0;ks<2;++ks){
            #pragma unroll
            for(int ntp=0;ntp<2;++ntp){
                int grp = lane>>3;
                int tile = ntp*2 + (grp>>1);
                int n = warpN*32 + tile*8 + (lane&7);
                int cc = (ks*2 + (grp&1)) ^ ((n>>1)&3);
                uint32_t ad = sb + 16384u + (uint32_t)(n*64 + cc*16);
                uint32_t t[4];
                ldsm4(t, ad);
                bf[ks][0][2*ntp][0]=t[0]; bf[ks][0][2*ntp][1]=t[1];
                bf[ks][0][2*ntp+1][0]=t[2]; bf[ks][0][2*ntp+1][1]=t[3];
                ldsm4(t, ad + 8192);
                bf[ks][1][2*ntp][0]=t[0]; bf[ks][1][2*ntp][1]=t[1];
                bf[ks][1][2*ntp+1][0]=t[2]; bf[ks][1][2*ntp+1][1]=t[3];
            }
        }

        auto ldA=[&](int idx, uint32_t* a0, uint32_t* a1){
            int ks = idx>>2, mt = idx&3;
            int r = warpM*64 + mt*16 + (lane&15);
            int cc = (ks*2 + (lane>>4)) ^ ((r>>1)&3);
            uint32_t ad = sb + (uint32_t)(r*64 + cc*16);
            ldsm4(a0, ad);
            ldsm4(a1, ad + 8192);
        };

        uint32_t Abuf[2][2][4];
        ldA(0, Abuf[0][0], Abuf[0][1]);
        #pragma unroll
        for(int idx=0; idx<8; ++idx){
            int ks = idx>>2, mt = idx&3;
            int cur = idx&1, nx = cur^1;
            if(idx<7) ldA(idx+1, Abuf[nx][0], Abuf[nx][1]);
            #pragma unroll
            for(int nt=0;nt<4;++nt) mma16816(acc[mt][nt], Abuf[cur][0], bf[ks][0][nt]); // hi*hi
            #pragma unroll
            for(int nt=0;nt<4;++nt) mma16816(acc[mt][nt], Abuf[cur][0], bf[ks][1][nt]); // hi*lo
            #pragma unroll
            for(int nt=0;nt<4;++nt) mma16816(acc[mt][nt], Abuf[cur][1], bf[ks][0][nt]); // lo*hi
        }
    }

    #pragma unroll
    for(int mt=0;mt<4;++mt){
        #pragma unroll
        for(int nt=0;nt<4;++nt){
            int rl = warpM*64 + mt*16 + (lane>>2);
            int cl = warpN*32 + nt*8 + (lane&3)*2;
            #pragma unroll
            for(int h=0;h<2;++h){
                int row = Mbase + rl + h*8;
                float v0 = acc[mt][nt][2*h]   + sbias[cl];
                float v1 = acc[mt][nt][2*h+1] + sbias[cl+1];
                if(relu){ v0=fmaxf(v0,0.f); v1=fmaxf(v1,0.f); }
                __nv_bfloat16 h0=__float2bfloat16(v0), h1=__float2bfloat16(v1);
                __nv_bfloat162 hv; hv.x=h0; hv.y=h1;
                __nv_bfloat162 lv; lv.x=__float2bfloat16(v0-__bfloat162float(h0));
                                   lv.y=__float2bfloat16(v1-__bfloat162float(h1));
                size_t o = (size_t)row*HDIM + Nbase + cl;
                *reinterpret_cast<uint32_t*>(oH+o) = *reinterpret_cast<uint32_t*>(&hv);
                *reinterpret_cast<uint32_t*>(oL+o) = *reinterpret_cast<uint32_t*>(&lv);
            }
        }
    }
}

// ---------------- transpose + hi/lo split ----------------
__global__ void transpose_split(const float* __restrict__ src, int KD, int ND, int KOUT,
                                __nv_bfloat16* __restrict__ dH, __nv_bfloat16* __restrict__ dL)
{
    __shared__ float t[32][33];
    const int mz=blockIdx.z;
    src+=(size_t)mz*KD*ND; dH+=(size_t)mz*ND*KOUT; dL+=(size_t)mz*ND*KOUT;
    const int kt=blockIdx.x*32, nt=blockIdx.y*32, tx=threadIdx.x, ty=threadIdx.y;
    for(int r=ty;r<32;r+=8){ int k=kt+r; t[r][tx]=(k<KD)?src[(size_t)k*ND+nt+tx]:0.f; }
    __syncthreads();
    for(int r=ty;r<32;r+=8){ int n=nt+r, k=kt+tx;
        float v=t[tx][r]; __nv_bfloat16 h=__float2bfloat16(v);
        dH[(size_t)n*KOUT+k]=h; dL[(size_t)n*KOUT+k]=__float2bfloat16(v-__bfloat162float(h)); }
}

// ---------------- init prev ----------------
__global__ void init_prev_k(const float* __restrict__ x,
                            __nv_bfloat16* __restrict__ phi, __nv_bfloat16* __restrict__ plo)
{
    int i=blockIdx.x*256+threadIdx.x; if(i>=BATCH*KP) return;
    int b=i>>7, c=i&127;
    float v=(c<IN_DIM)?x[b*IN_DIM+c]:0.f;
    __nv_bfloat16 h=__float2bfloat16(v);
    __nv_bfloat16 l=__float2bfloat16(v-__bfloat162float(h));
    size_t o2=(size_t)BATCH*KP;
    phi[i]=h; plo[i]=l; phi[i+o2]=h; plo[i+o2]=l;
}

// ---------------- out-proj (fully-resolved pointers, one direction) ----------------
__global__ void out_proj(const __nv_bfloat16* __restrict__ hHi, const __nv_bfloat16* __restrict__ hLo,
                         const float* __restrict__ Wout, const float* __restrict__ bout,
                         float* __restrict__ tot,
                         __nv_bfloat16* __restrict__ ph, __nv_bfloat16* __restrict__ pl,
                         int level)
{
    const int b=blockIdx.x, tid=threadIdx.x;
    const size_t hoff=(size_t)b*HDIM;

    __shared__ float sh[HDIM];
    #pragma unroll
    for(int q=0;q<4;++q){ int k=tid+q*256;
        sh[k]=__bfloat162float(hHi[hoff+k])+__bfloat162float(hLo[hoff+k]); }
    __syncthreads();
    const int warp=tid>>5, lane=tid&31;
    if(warp<ODIM){
        float acc=0.f;
        for(int k=lane;k<HDIM;k+=32) acc+=sh[k]*Wout[k*ODIM+warp];
        #pragma unroll
        for(int off=16;off>0;off>>=1) acc+=__shfl_down_sync(0xffffffffu,acc,off);
        if(lane==0){
            float val=acc+bout[warp];
            tot[b*TOTW+level*ODIM+warp]=val;
            if(level<LEVELS-1){
                int pc=b*KP+IN_DIM+level*ODIM+warp;
                __nv_bfloat16 h=__float2bfloat16(val);
                ph[pc]=h; pl[pc]=__float2bfloat16(val-__bfloat162float(h));
            }
        }
    }
}

// ---------------- attention + final linear ----------------
__global__ void attn_final(const float* __restrict__ totbuf,
                           const float* __restrict__ W1, const float* __restrict__ W2,
                           const float* __restrict__ W3, const float* __restrict__ W4,
                           const float* __restrict__ b4, float* __restrict__ out)
{
    const int b=blockIdx.x;
    const float* totF=totbuf; const float* totB=totbuf+(size_t)BATCH*TOTW;
    __shared__ float tf[ODIM][LEVELS], tb[ODIM][LEVELS];
    __shared__ float q[LEVELS][ODIM], kk[ODIM][LEVELS], v[LEVELS][ODIM];
    __shared__ float attn[LEVELS][LEVELS], res[TOTW], w1[25], w2[25], w3[25];
    const int tid=threadIdx.x;
    if(tid<TOTW){
        reinterpret_cast<float*>(tf)[tid]=totF[b*TOTW+tid];
        int d=tid/LEVELS, t=tid%LEVELS;
        tb[d][t]=totB[b*TOTW+d*LEVELS+(LEVELS-1-t)];
    }
    if(tid<25){ w1[tid]=W1[tid]; w2[tid]=W2[tid]; w3[tid]=W3[tid]; }
    __syncthreads();
    if(tid<TOTW){
        int t=tid/ODIM, e=tid%ODIM;
        float sq=0.f,sk=0.f,sv=0.f;
        #pragma unroll
        for(int d=0;d<ODIM;++d){
            sq+=tf[d][t]*w1[d*ODIM+e]; sk+=tb[d][t]*w2[d*ODIM+e]; sv+=tb[d][t]*w3[d*ODIM+e]; }
        q[t][e]=sq; kk[e][t]=sk; v[t][e]=sv;
    }
    __syncthreads();
    for(int idx=tid;idx<LEVELS*LEVELS;idx+=blockDim.x){
        int t=idx/LEVELS, s=idx%LEVELS;
        float sc=0.f;
        #pragma unroll
        for(int e=0;e<ODIM;++e) sc+=q[t][e]*kk[e][s];
        attn[t][s]=sc;
    }
    __syncthreads();
    if(tid<LEVELS){
        int s=tid; float mx=-1e30f;
        for(int t=0;t<LEVELS;++t) mx=fmaxf(mx,attn[t][s]);
        float sm=0.f;
        for(int t=0;t<LEVELS;++t){ float e=expf(attn[t][s]-mx); attn[t][s]=e; sm+=e; }
        float inv=1.f/sm;
        for(int t=0;t<LEVELS;++t) attn[t][s]*=inv;
    }
    __syncthreads();
    if(tid<TOTW){
        int t=tid/ODIM, e=tid%ODIM; float r=0.f;
        for(int s=0;s<LEVELS;++s) r+=attn[t][s]*v[s][e];
        res[tid]=r;
    }
    __syncthreads();
    if(tid<TOTW){
        int o=tid; float y=b4[o];
        for(int j=0;j<TOTW;++j) y+=res[j]*W4[j*TOTW+o];
        out[(size_t)b*TOTW+o]=y;
    }
}

// ---------------- host ----------------
extern "C" void kernel_launch(void* const* d_in, const int* in_sizes, int n_in,
                              void* d_out, int out_size)
{
    const float* x=(const float*)d_in[0];
    const float* Win_f=(const float*)d_in[1];  const float* bin_f=(const float*)d_in[2];
    const float* Win_b=(const float*)d_in[3];  const float* bin_b=(const float*)d_in[4];
    const float* Wblk=(const float*)d_in[5];   const float* bblk=(const float*)d_in[6];
    const float* Wout_f=(const float*)d_in[7]; const float* bout_f=(const float*)d_in[8];
    const float* Wout_b=(const float*)d_in[9]; const float* bout_b=(const float*)d_in[10];
    const float* W1=(const float*)d_in[11]; const float* W2=(const float*)d_in[12];
    const float* W3=(const float*)d_in[13]; const float* W4=(const float*)d_in[14];
    const float* b4=(const float*)d_in[15];
    float* out=(float*)d_out;

    __nv_bfloat16 *hhi,*hlo,*phi,*plo,*wihi,*wilo,*wbhi,*wblo; float* tot;
    cudaGetSymbolAddress((void**)&hhi,g_hhi);   cudaGetSymbolAddress((void**)&hlo,g_hlo);
    cudaGetSymbolAddress((void**)&phi,g_phi);   cudaGetSymbolAddress((void**)&plo,g_plo);
    cudaGetSymbolAddress((void**)&wihi,g_wihi); cudaGetSymbolAddress((void**)&wilo,g_wilo);
    cudaGetSymbolAddress((void**)&wbhi,g_wbhi); cudaGetSymbolAddress((void**)&wblo,g_wblo);
    cudaGetSymbolAddress((void**)&tot,g_tot);

    cudaFuncSetAttribute(gemm_bf16x3, cudaFuncAttributeMaxDynamicSharedMemorySize, SMEM_DYN);

    // fork a second stream for the backward-direction chain (capture-safe fork/join)
    cudaStream_t sB;
    cudaStreamCreateWithFlags(&sB, cudaStreamNonBlocking);
    cudaEvent_t eFork, eJoin;
    cudaEventCreateWithFlags(&eFork, cudaEventDisableTiming);
    cudaEventCreateWithFlags(&eJoin, cudaEventDisableTiming);

    const size_t WI=(size_t)HDIM*KP;
    transpose_split<<<dim3(KP/32,HDIM/32,LEVELS),dim3(32,8)>>>(Win_f,96,HDIM,KP,wihi,wilo);
    transpose_split<<<dim3(KP/32,HDIM/32,LEVELS),dim3(32,8)>>>(Win_b,96,HDIM,KP,wihi+17*WI,wilo+17*WI);
    transpose_split<<<dim3(HDIM/32,HDIM/32,HS),dim3(32,8)>>>(Wblk,HDIM,HDIM,HDIM,wbhi,wblo);
    init_prev_k<<<(BATCH*KP+255)/256,256>>>(x,phi,plo);

    cudaEventRecord(eFork, 0);
    cudaStreamWaitEvent(sB, eFork, 0);

    dim3 gg(HDIM/128, BATCH/128, 1);  // (8, 32, 1): 256 CTAs per direction
    const size_t PK=(size_t)BATCH*KP, WB=(size_t)HDIM*HDIM;

    for(int i=0;i<LEVELS;++i){
        // ---- forward direction on default stream ----
        gemm_bf16x3<<<gg,256,SMEM_DYN,0>>>(phi,plo,phi,plo,KP,
            wihi+(size_t)i*WI, wilo+(size_t)i*WI, wihi+(size_t)i*WI, wilo+(size_t)i*WI,
            bin_f+i*HDIM, bin_f+i*HDIM,
            hhi, hlo, hhi, hlo, KP, 0);
        // ---- backward direction on sB ----
        gemm_bf16x3<<<gg,256,SMEM_DYN,sB>>>(phi+PK,plo+PK,phi+PK,plo+PK,KP,
            wihi+(size_t)(17+i)*WI, wilo+(size_t)(17+i)*WI, wihi+(size_t)(17+i)*WI, wilo+(size_t)(17+i)*WI,
            bin_b+i*HDIM, bin_b+i*HDIM,
            hhi+2ull*HN, hlo+2ull*HN, hhi+2ull*HN, hlo+2ull*HN, KP, 0);

        int cur=0;
        for(int j=0;j<HS;++j){
            gemm_bf16x3<<<gg,256,SMEM_DYN,0>>>(
                hhi+(size_t)cur*HN, hlo+(size_t)cur*HN, hhi+(size_t)cur*HN, hlo+(size_t)cur*HN, HDIM,
                wbhi+(size_t)j*WB, wblo+(size_t)j*WB, wbhi+(size_t)j*WB, wblo+(size_t)j*WB,
                bblk+j*HDIM, bblk+j*HDIM,
                hhi+(size_t)(cur^1)*HN, hlo+(size_t)(cur^1)*HN,
                hhi+(size_t)(cur^1)*HN, hlo+(size_t)(cur^1)*HN, HDIM, 1);
            gemm_bf16x3<<<gg,256,SMEM_DYN,sB>>>(
                hhi+(size_t)(2+cur)*HN, hlo+(size_t)(2+cur)*HN, hhi+(size_t)(2+cur)*HN, hlo+(size_t)(2+cur)*HN, HDIM,
                wbhi+(size_t)j*WB, wblo+(size_t)j*WB, wbhi+(size_t)j*WB, wblo+(size_t)j*WB,
                bblk+j*HDIM, bblk+j*HDIM,
                hhi+(size_t)(2+(cur^1))*HN, hlo+(size_t)(2+(cur^1))*HN,
                hhi+(size_t)(2+(cur^1))*HN, hlo+(size_t)(2+(cur^1))*HN, HDIM, 1);
            cur^=1;
        }
        // after 3 block layers result is in buffer 1 (F) / 3 (B)
        out_proj<<<dim3(BATCH,1,1),256,0,0>>>(hhi+1ull*HN, hlo+1ull*HN,
            Wout_f+(size_t)i*HDIM*ODIM, bout_f+i*ODIM, tot, phi, plo, i);
        out_proj<<<dim3(BATCH,1,1),256,0,sB>>>(hhi+3ull*HN, hlo+3ull*HN,
            Wout_b+(size_t)i*HDIM*ODIM, bout_b+i*ODIM, tot+(size_t)BATCH*TOTW, phi+PK, plo+PK, i);
    }

    cudaEventRecord(eJoin, sB);
    cudaStreamWaitEvent(0, eJoin, 0);

    attn_final<<<BATCH,128>>>(tot,W1,W2,W3,W4,b4,out);
    // streams/events intentionally not destroyed: kernel_launch is invoked only
    // for correctness + capture; destroying a forked stream mid-capture would
    // invalidate the capture sequence.
}

// round 11
// speedup vs baseline: 4.5600x; 1.3569x over previous
#include <cuda_runtime.h>
#include <cuda_bf16.h>
#include <cstdint>

#define BATCH 4096
#define IN_DIM 16
#define LEVELS 17
#define ODIM 5
#define HDIM 1024
#define HS 3
#define KP 128
#define TOTW (ODIM*LEVELS)
#define HN (BATCH*HDIM)
#define WI ((size_t)KP*HDIM)      // 131072: per-level Win-pad / WcombT size
#define WB ((size_t)HDIM*HDIM)

// ---------------- scratch ----------------
__device__ __nv_bfloat16 g_hhi[4ull*HN], g_hlo[4ull*HN];
__device__ __nv_bfloat16 g_phi[2ull*BATCH*KP], g_plo[2ull*BATCH*KP];
__device__ __nv_bfloat16 g_wphi[34ull*WI], g_wplo[34ull*WI];   // Win padded [z][128][1024]
__device__ __nv_bfloat16 g_wchi[34ull*WI], g_wclo[34ull*WI];   // WcombT    [z][1024][128]
__device__ __nv_bfloat16 g_wbhi[3ull*WB], g_wblo[3ull*WB];     // WblkT     [j][1024][1024]
__device__ float g_bcomb[34ull*HDIM];
__device__ float g_zero[128];                                   // zero-initialized
__device__ float g_tot[2ull*BATCH*TOTW];

// ---------------- helpers ----------------
__device__ __forceinline__ uint32_t smem_u32(const void* p){ return (uint32_t)__cvta_generic_to_shared(p); }
__device__ __forceinline__ void cpa16(uint32_t d, const void* s){
    asm volatile("cp.async.cg.shared.global [%0], [%1], 16;" :: "r"(d),"l"(s)); }
#define CP_COMMIT() asm volatile("cp.async.commit_group;" ::: "memory")

__device__ __forceinline__ void ldsm4(uint32_t* r, uint32_t a){
    asm volatile("ldmatrix.sync.aligned.m8n8.x4.shared.b16 {%0,%1,%2,%3}, [%4];"
        : "=r"(r[0]),"=r"(r[1]),"=r"(r[2]),"=r"(r[3]) : "r"(a));
}
__device__ __forceinline__ void mma16816(float* d, const uint32_t* a, const uint32_t* b){
    asm("mma.sync.aligned.m16n8k16.row.col.f32.bf16.bf16.f32 "
        "{%0,%1,%2,%3}, {%4,%5,%6,%7}, {%8,%9}, {%0,%1,%2,%3};"
        : "+f"(d[0]),"+f"(d[1]),"+f"(d[2]),"+f"(d[3])
        : "r"(a[0]),"r"(a[1]),"r"(a[2]),"r"(a[3]), "r"(b[0]),"r"(b[1]));
}

// ---------------- GEMM: C[M x N] = act(A @ B^T + bias), bf16x3 via mma.sync ----------------
// A[M,AKD] hi/lo row-major; B[N,AKD] hi/lo (pre-transposed). Output bf16 hi/lo, row stride ldo.
// blockIdx.z batches independent problems via element strides aZ/bZ/oZ (bias strided by biasZ).
#define STG_SZ 32768
#define SMEM_DYN (3*STG_SZ)

__global__ void __launch_bounds__(256, 2)
gemm_bf16x3(const __nv_bfloat16* __restrict__ Ah, const __nv_bfloat16* __restrict__ Al,
            int AKD, size_t aZ,
            const __nv_bfloat16* __restrict__ Bh, const __nv_bfloat16* __restrict__ Bl, size_t bZ,
            const float* __restrict__ bias, size_t biasZ,
            __nv_bfloat16* __restrict__ oH, __nv_bfloat16* __restrict__ oL, size_t oZ, int ldo,
            int K, int relu)
{
    extern __shared__ char smem[];
    __shared__ float sbias[128];
    const int tid=threadIdx.x, wid=tid>>5, lane=tid&31;
    const size_t z=blockIdx.z;
    Ah+=z*aZ; Al+=z*aZ; Bh+=z*bZ; Bl+=z*bZ; oH+=z*oZ; oL+=z*oZ; bias+=z*biasZ;

    const int Nbase=blockIdx.x*128, Mbase=blockIdx.y*128;
    const int warpM=wid&1, warpN=wid>>1;

    if(tid<128) sbias[tid]=bias[Nbase+tid];
    const uint32_t sbase=smem_u32(smem);

    auto load_stage=[&](int s){
        const uint32_t sb = sbase + (uint32_t)(s%3)*STG_SZ;
        const int kb = s*32;
        #pragma unroll
        for(int i=0;i<2;++i){
            int idx = tid + i*256;
            int r = idx>>2, c = idx&3;
            uint32_t dst = sb + (uint32_t)(r*64 + ((c ^ ((r>>1)&3))*16));
            size_t ga = (size_t)(Mbase+r)*AKD + kb + c*8;
            size_t gb = (size_t)(Nbase+r)*AKD + kb + c*8;
            cpa16(dst,         Ah+ga);
            cpa16(dst+8192,    Al+ga);
            cpa16(dst+16384,   Bh+gb);
            cpa16(dst+24576,   Bl+gb);
        }
        CP_COMMIT();
    };

    float acc[4][4][4];
    #pragma unroll
    for(int m=0;m<4;++m)
        #pragma unroll
        for(int n=0;n<4;++n)
            #pragma unroll
            for(int i=0;i<4;++i) acc[m][n][i]=0.f;

    const int NS = K>>5;
    load_stage(0); load_stage(1);

    for(int s=0;s<NS;++s){
        if(s+1<NS) asm volatile("cp.async.wait_group 1;":::"memory");
        else       asm volatile("cp.async.wait_group 0;":::"memory");
        __syncthreads();
        if(s+2<NS) load_stage(s+2);

        const uint32_t sb = sbase + (uint32_t)(s%3)*STG_SZ;

        uint32_t bf[2][2][4][2];   // [ks][hi/lo][ntile][2]
        #pragma unroll
        for(int ks=0;ks<2;++ks){
            #pragma unroll
            for(int ntp=0;ntp<2;++ntp){
                int grp = lane>>3;
                int tile = ntp*2 + (grp>>1);
                int n = warpN*32 + tile*8 + (lane&7);
                int cc = (ks*2 + (grp&1)) ^ ((n>>1)&3);
                uint32_t ad = sb + 16384u + (uint32_t)(n*64 + cc*16);
                uint32_t t[4];
                ldsm4(t, ad);
                bf[ks][0][2*ntp][0]=t[0]; bf[ks][0][2*ntp][1]=t[1];
                bf[ks][0][2*ntp+1][0]=t[2]; bf[ks][0][2*ntp+1][1]=t[3];
                ldsm4(t, ad + 8192);
                bf[ks][1][2*ntp][0]=t[0]; bf[ks][1][2*ntp][1]=t[1];
                bf[ks][1][2*ntp+1][0]=t[2]; bf[ks][1][2*ntp+1][1]=t[3];
            }
        }

        auto ldA=[&](int idx, uint32_t* a0, uint32_t* a1){
            int ks = idx>>2, mt = idx&3;
            int r = warpM*64 + mt*16 + (lane&15);
            int cc = (ks*2 + (lane>>4)) ^ ((r>>1)&3);
            uint32_t ad = sb + (uint32_t)(r*64 + cc*16);
            ldsm4(a0, ad);
            ldsm4(a1, ad + 8192);
        };

        uint32_t Abuf[2][2][4];
        ldA(0, Abuf[0][0], Abuf[0][1]);
        #pragma unroll
        for(int idx=0; idx<8; ++idx){
            int ks = idx>>2, mt = idx&3;
            int cur = idx&1, nx = cur^1;
            if(idx<7) ldA(idx+1, Abuf[nx][0], Abuf[nx][1]);
            #pragma unroll
            for(int nt=0;nt<4;++nt) mma16816(acc[mt][nt], Abuf[cur][0], bf[ks][0][nt]); // hi*hi
            #pragma unroll
            for(int nt=0;nt<4;++nt) mma16816(acc[mt][nt], Abuf[cur][0], bf[ks][1][nt]); // hi*lo
            #pragma unroll
            for(int nt=0;nt<4;++nt) mma16816(acc[mt][nt], Abuf[cur][1], bf[ks][0][nt]); // lo*hi
        }
    }

    #pragma unroll
    for(int mt=0;mt<4;++mt){
        #pragma unroll
        for(int nt=0;nt<4;++nt){
            int rl = warpM*64 + mt*16 + (lane>>2);
            int cl = warpN*32 + nt*8 + (lane&3)*2;
            #pragma unroll
            for(int h=0;h<2;++h){
                int row = Mbase + rl + h*8;
                float v0 = acc[mt][nt][2*h]   + sbias[cl];
                float v1 = acc[mt][nt][2*h+1] + sbias[cl+1];
                if(relu){ v0=fmaxf(v0,0.f); v1=fmaxf(v1,0.f); }
                __nv_bfloat16 h0=__float2bfloat16(v0), h1=__float2bfloat16(v1);
                __nv_bfloat162 hv; hv.x=h0; hv.y=h1;
                __nv_bfloat162 lv; lv.x=__float2bfloat16(v0-__bfloat162float(h0));
                                   lv.y=__float2bfloat16(v1-__bfloat162float(h1));
                size_t o = (size_t)row*ldo + Nbase + cl;
                *reinterpret_cast<uint32_t*>(oH+o) = *reinterpret_cast<uint32_t*>(&hv);
                *reinterpret_cast<uint32_t*>(oL+o) = *reinterpret_cast<uint32_t*>(&lv);
            }
        }
    }
}

// ---------------- transpose + hi/lo split: dst[n][k]=split(src[k][n]) ----------------
__global__ void transpose_split(const float* __restrict__ src, int KD, int ND, int KOUT,
                                __nv_bfloat16* __restrict__ dH, __nv_bfloat16* __restrict__ dL)
{
    __shared__ float t[32][33];
    const int mz=blockIdx.z;
    src+=(size_t)mz*KD*ND; dH+=(size_t)mz*ND*KOUT; dL+=(size_t)mz*ND*KOUT;
    const int kt=blockIdx.x*32, nt=blockIdx.y*32, tx=threadIdx.x, ty=threadIdx.y;
    for(int r=ty;r<32;r+=8){ int k=kt+r; t[r][tx]=(k<KD)?src[(size_t)k*ND+nt+tx]:0.f; }
    __syncthreads();
    for(int r=ty;r<32;r+=8){ int n=nt+r, k=kt+tx;
        float v=t[tx][r]; __nv_bfloat16 h=__float2bfloat16(v);
        dH[(size_t)n*KOUT+k]=h; dL[(size_t)n*KOUT+k]=__float2bfloat16(v-__bfloat162float(h)); }
}

// ---------------- plain split with row pad: out[z][k<128][j] = k<96 ? split(Win[z][k][j]) : 0 ----------------
__global__ void split_pad(const float* __restrict__ src,
                          __nv_bfloat16* __restrict__ dH, __nv_bfloat16* __restrict__ dL)
{
    size_t i = (size_t)blockIdx.x*256 + threadIdx.x;
    if(i >= 17ull*WI) return;
    size_t z = i / WI; size_t rem = i % WI;
    int k = (int)(rem / HDIM), j = (int)(rem % HDIM);
    float v = (k < 96) ? src[(z*96 + k)*HDIM + j] : 0.f;
    __nv_bfloat16 h = __float2bfloat16(v);
    dH[i] = h; dL[i] = __float2bfloat16(v - __bfloat162float(h));
}

// ---------------- bcomb[z][n] = sum_j bin[z][j]*Wblk0[j][n] + bblk0[n]  (fp32 exact) ----------------
__global__ void bcomb_k(const float* __restrict__ bin_f, const float* __restrict__ bin_b,
                        const float* __restrict__ Wblk, const float* __restrict__ bblk,
                        float* __restrict__ bcomb)
{
    int n = blockIdx.x*256 + threadIdx.x;     // grid.x = 4
    int z = blockIdx.y;                        // 0..33
    const float* bin = (z < 17) ? (bin_f + (size_t)z*HDIM) : (bin_b + (size_t)(z-17)*HDIM);
    float acc = bblk[n];
    for(int j=0;j<HDIM;++j) acc += bin[j]*Wblk[(size_t)j*HDIM + n];
    bcomb[(size_t)z*HDIM + n] = acc;
}

// ---------------- init prev ----------------
__global__ void init_prev_k(const float* __restrict__ x,
                            __nv_bfloat16* __restrict__ phi, __nv_bfloat16* __restrict__ plo)
{
    int i=blockIdx.x*256+threadIdx.x; if(i>=BATCH*KP) return;
    int b=i>>7, c=i&127;
    float v=(c<IN_DIM)?x[b*IN_DIM+c]:0.f;
    __nv_bfloat16 h=__float2bfloat16(v);
    __nv_bfloat16 l=__float2bfloat16(v-__bfloat162float(h));
    size_t o2=(size_t)BATCH*KP;
    phi[i]=h; plo[i]=l; phi[i+o2]=h; plo[i+o2]=l;
}

// ---------------- out-proj ----------------
__global__ void out_proj(const __nv_bfloat16* __restrict__ hHi, const __nv_bfloat16* __restrict__ hLo,
                         const float* __restrict__ Wout, const float* __restrict__ bout,
                         float* __restrict__ tot,
                         __nv_bfloat16* __restrict__ ph, __nv_bfloat16* __restrict__ pl,
                         int level)
{
    const int b=blockIdx.x, tid=threadIdx.x;
    const size_t hoff=(size_t)b*HDIM;
    __shared__ float sh[HDIM];
    #pragma unroll
    for(int q=0;q<4;++q){ int k=tid+q*256;
        sh[k]=__bfloat162float(hHi[hoff+k])+__bfloat162float(hLo[hoff+k]); }
    __syncthreads();
    const int warp=tid>>5, lane=tid&31;
    if(warp<ODIM){
        float acc=0.f;
        for(int k=lane;k<HDIM;k+=32) acc+=sh[k]*Wout[k*ODIM+warp];
        #pragma unroll
        for(int off=16;off>0;off>>=1) acc+=__shfl_down_sync(0xffffffffu,acc,off);
        if(lane==0){
            float val=acc+bout[warp];
            tot[b*TOTW+level*ODIM+warp]=val;
            if(level<LEVELS-1){
                int pc=b*KP+IN_DIM+level*ODIM+warp;
                __nv_bfloat16 h=__float2bfloat16(val);
                ph[pc]=h; pl[pc]=__float2bfloat16(val-__bfloat162float(h));
            }
        }
    }
}

// ---------------- attention + final linear ----------------
__global__ void attn_final(const float* __restrict__ totbuf,
                           const float* __restrict__ W1, const float* __restrict__ W2,
                           const float* __restrict__ W3, const float* __restrict__ W4,
                           const float* __restrict__ b4, float* __restrict__ out)
{
    const int b=blockIdx.x;
    const float* totF=totbuf; const float* totB=totbuf+(size_t)BATCH*TOTW;
    __shared__ float tf[ODIM][LEVELS], tb[ODIM][LEVELS];
    __shared__ float q[LEVELS][ODIM], kk[ODIM][LEVELS], v[LEVELS][ODIM];
    __shared__ float attn[LEVELS][LEVELS], res[TOTW], w1[25], w2[25], w3[25];
    const int tid=threadIdx.x;
    if(tid<TOTW){
        reinterpret_cast<float*>(tf)[tid]=totF[b*TOTW+tid];
        int d=tid/LEVELS, t=tid%LEVELS;
        tb[d][t]=totB[b*TOTW+d*LEVELS+(LEVELS-1-t)];
    }
    if(tid<25){ w1[tid]=W1[tid]; w2[tid]=W2[tid]; w3[tid]=W3[tid]; }
    __syncthreads();
    if(tid<TOTW){
        int t=tid/ODIM, e=tid%ODIM;
        float sq=0.f,sk=0.f,sv=0.f;
        #pragma unroll
        for(int d=0;d<ODIM;++d){
            sq+=tf[d][t]*w1[d*ODIM+e]; sk+=tb[d][t]*w2[d*ODIM+e]; sv+=tb[d][t]*w3[d*ODIM+e]; }
        q[t][e]=sq; kk[e][t]=sk; v[t][e]=sv;
    }
    __syncthreads();
    for(int idx=tid;idx<LEVELS*LEVELS;idx+=blockDim.x){
        int t=idx/LEVELS, s=idx%LEVELS;
        float sc=0.f;
        #pragma unroll
        for(int e=0;e<ODIM;++e) sc+=q[t][e]*kk[e][s];
        attn[t][s]=sc;
    }
    __syncthreads();
    if(tid<LEVELS){
        int s=tid; float mx=-1e30f;
        for(int t=0;t<LEVELS;++t) mx=fmaxf(mx,attn[t][s]);
        float sm=0.f;
        for(int t=0;t<LEVELS;++t){ float e=expf(attn[t][s]-mx); attn[t][s]=e; sm+=e; }
        float inv=1.f/sm;
        for(int t=0;t<LEVELS;++t) attn[t][s]*=inv;
    }
    __syncthreads();
    if(tid<TOTW){
        int t=tid/ODIM, e=tid%ODIM; float r=0.f;
        for(int s=0;s<LEVELS;++s) r+=attn[t][s]*v[s][e];
        res[tid]=r;
    }
    __syncthreads();
    if(tid<TOTW){
        int o=tid; float y=b4[o];
        for(int j=0;j<TOTW;++j) y+=res[j]*W4[j*TOTW+o];
        out[(size_t)b*TOTW+o]=y;
    }
}

// ---------------- host ----------------
extern "C" void kernel_launch(void* const* d_in, const int* in_sizes, int n_in,
                              void* d_out, int out_size)
{
    const float* x=(const float*)d_in[0];
    const float* Win_f=(const float*)d_in[1];  const float* bin_f=(const float*)d_in[2];
    const float* Win_b=(const float*)d_in[3];  const float* bin_b=(const float*)d_in[4];
    const float* Wblk=(const float*)d_in[5];   const float* bblk=(const float*)d_in[6];
    const float* Wout_f=(const float*)d_in[7]; const float* bout_f=(const float*)d_in[8];
    const float* Wout_b=(const float*)d_in[9]; const float* bout_b=(const float*)d_in[10];
    const float* W1=(const float*)d_in[11]; const float* W2=(const float*)d_in[12];
    const float* W3=(const float*)d_in[13]; const float* W4=(const float*)d_in[14];
    const float* b4=(const float*)d_in[15];
    float* out=(float*)d_out;

    __nv_bfloat16 *hhi,*hlo,*phi,*plo,*wphi,*wplo,*wchi,*wclo,*wbhi,*wblo;
    float *tot,*bcomb,*zero;
    cudaGetSymbolAddress((void**)&hhi,g_hhi);   cudaGetSymbolAddress((void**)&hlo,g_hlo);
    cudaGetSymbolAddress((void**)&phi,g_phi);   cudaGetSymbolAddress((void**)&plo,g_plo);
    cudaGetSymbolAddress((void**)&wphi,g_wphi); cudaGetSymbolAddress((void**)&wplo,g_wplo);
    cudaGetSymbolAddress((void**)&wchi,g_wchi); cudaGetSymbolAddress((void**)&wclo,g_wclo);
    cudaGetSymbolAddress((void**)&wbhi,g_wbhi); cudaGetSymbolAddress((void**)&wblo,g_wblo);
    cudaGetSymbolAddress((void**)&tot,g_tot);   cudaGetSymbolAddress((void**)&bcomb,g_bcomb);
    cudaGetSymbolAddress((void**)&zero,g_zero);

    cudaFuncSetAttribute(gemm_bf16x3, cudaFuncAttributeMaxDynamicSharedMemorySize, SMEM_DYN);

    cudaStream_t sB;
    cudaStreamCreateWithFlags(&sB, cudaStreamNonBlocking);
    cudaEvent_t eFork, eJoin;
    cudaEventCreateWithFlags(&eFork, cudaEventDisableTiming);
    cudaEventCreateWithFlags(&eJoin, cudaEventDisableTiming);

    // ---- shared prep (default stream) ----
    transpose_split<<<dim3(HDIM/32,HDIM/32,HS),dim3(32,8)>>>(Wblk,HDIM,HDIM,HDIM,wbhi,wblo);
    split_pad<<<(int)((17ull*WI+255)/256),256>>>(Win_f, wphi,        wplo);
    split_pad<<<(int)((17ull*WI+255)/256),256>>>(Win_b, wphi+17*WI,  wplo+17*WI);
    bcomb_k<<<dim3(HDIM/256,34),256>>>(bin_f,bin_b,Wblk,bblk,bcomb);
    init_prev_k<<<(BATCH*KP+255)/256,256>>>(x,phi,plo);

    cudaEventRecord(eFork, 0);
    cudaStreamWaitEvent(sB, eFork, 0);

    // ---- precompute WcombT = Wblk0^T @ Win^T, batched over 17 levels per direction ----
    // C2[n,k] = sum_j WblkT0[n,j] * WinPad[k,j];  M=1024, N=128, K=1024, ldo=128
    gemm_bf16x3<<<dim3(1,HDIM/128,LEVELS),256,SMEM_DYN,0>>>(
        wbhi, wblo, HDIM, 0,
        wphi, wplo, WI,
        zero, 0,
        wchi, wclo, WI, KP, HDIM, 0);
    gemm_bf16x3<<<dim3(1,HDIM/128,LEVELS),256,SMEM_DYN,sB>>>(
        wbhi, wblo, HDIM, 0,
        wphi+17*WI, wplo+17*WI, WI,
        zero, 0,
        wchi+17*WI, wclo+17*WI, WI, KP, HDIM, 0);

    dim3 gg(HDIM/128, BATCH/128, 1);
    const size_t PK=(size_t)BATCH*KP;

    for(int i=0;i<LEVELS;++i){
        // fused level-entry GEMM: h0 = relu(prev @ WcombT^T + bcomb), K=128
        gemm_bf16x3<<<gg,256,SMEM_DYN,0>>>(phi,plo,KP,0,
            wchi+(size_t)i*WI, wclo+(size_t)i*WI, 0,
            bcomb+(size_t)i*HDIM, 0,
            hhi, hlo, 0, HDIM, KP, 1);
        gemm_bf16x3<<<gg,256,SMEM_DYN,sB>>>(phi+PK,plo+PK,KP,0,
            wchi+(size_t)(17+i)*WI, wclo+(size_t)(17+i)*WI, 0,
            bcomb+(size_t)(17+i)*HDIM, 0,
            hhi+2ull*HN, hlo+2ull*HN, 0, HDIM, KP, 1);

        int cur=0;
        for(int j=1;j<HS;++j){
            gemm_bf16x3<<<gg,256,SMEM_DYN,0>>>(
                hhi+(size_t)cur*HN, hlo+(size_t)cur*HN, HDIM, 0,
                wbhi+(size_t)j*WB, wblo+(size_t)j*WB, 0,
                bblk+(size_t)j*HDIM, 0,
                hhi+(size_t)(cur^1)*HN, hlo+(size_t)(cur^1)*HN, 0, HDIM, HDIM, 1);
            gemm_bf16x3<<<gg,256,SMEM_DYN,sB>>>(
                hhi+(size_t)(2+cur)*HN, hlo+(size_t)(2+cur)*HN, HDIM, 0,
                wbhi+(size_t)j*WB, wblo+(size_t)j*WB, 0,
                bblk+(size_t)j*HDIM, 0,
                hhi+(size_t)(2+(cur^1))*HN, hlo+(size_t)(2+(cur^1))*HN, 0, HDIM, HDIM, 1);
            cur^=1;
        }
        // after fused + 2 block layers, result is in buffer 0 (F) / 2 (B)
        out_proj<<<dim3(BATCH,1,1),256,0,0>>>(hhi, hlo,
            Wout_f+(size_t)i*HDIM*ODIM, bout_f+i*ODIM, tot, phi, plo, i);
        out_proj<<<dim3(BATCH,1,1),256,0,sB>>>(hhi+2ull*HN, hlo+2ull*HN,
            Wout_b+(size_t)i*HDIM*ODIM, bout_b+i*ODIM, tot+(size_t)BATCH*TOTW, phi+PK, plo+PK, i);
    }

    cudaEventRecord(eJoin, sB);
    cudaStreamWaitEvent(0, eJoin, 0);

    attn_final<<<BATCH,128>>>(tot,W1,W2,W3,W4,b4,out);
    // streams/events intentionally not destroyed (capture-safe; no device memory involved)
}